// round 8
// baseline (speedup 1.0000x reference)
#include <cuda_runtime.h>
#include <cuda_bf16.h>
#include <cstdint>

#define NN 50000
#define EE 800000
#define TOT (EE + NN)

// ---------------- scratch (static device globals; no allocations) ----------------
__device__ float    g_h[2][(size_t)NN * 128];    // per-chain GEMM output
__device__ float    g_z1[2][(size_t)NN * 128];   // xZ1 (real), xfZ1 (fake)
__device__ uint32_t g_xh[2][(size_t)NN * 128];   // tf32 hi of gemm input, per chain
__device__ uint32_t g_xl[2][(size_t)NN * 128];   // tf32 lo of gemm input, per chain
__device__ uint32_t g_wh[2][128 * 128];          // tf32 hi of W, per layer
__device__ uint32_t g_wl[2][128 * 128];          // tf32 lo of W, per layer
__device__ float    g_as[2][NN * 2];             // alpha_src per node per head
__device__ float    g_ad[2][NN * 2];             // alpha_dst per node per head
__device__ int      g_counts[2][NN];
__device__ int      g_rowstart[2][NN + 1];
__device__ int      g_cursor[2][NN];
__device__ int      g_csr[2][TOT];               // incoming-edge source lists (CSR by dst)

__device__ __forceinline__ float lrelu(float v, float s) { return v > 0.f ? v : s * v; }

__device__ __forceinline__ uint32_t to_tf32(float f) {
    uint32_t r;
    asm("cvt.rna.tf32.f32 %0, %1;" : "=r"(r) : "f"(f));
    return r;
}
__device__ __forceinline__ void split_tf32(float f, uint32_t& h, uint32_t& l) {
    h = to_tf32(f);
    l = to_tf32(f - __uint_as_float(h));
}

__device__ __forceinline__ void mma_tf32(float* d, const uint32_t* a, const uint32_t* b) {
    asm volatile(
        "mma.sync.aligned.m16n8k8.row.col.f32.tf32.tf32.f32 "
        "{%0,%1,%2,%3}, {%4,%5,%6,%7}, {%8,%9}, {%0,%1,%2,%3};\n"
        : "+f"(d[0]), "+f"(d[1]), "+f"(d[2]), "+f"(d[3])
        : "r"(a[0]), "r"(a[1]), "r"(a[2]), "r"(a[3]), "r"(b[0]), "r"(b[1]));
}

// ---------------- pre-split kernels ----------------
__global__ void split_w_kernel(const float* __restrict__ W, int layer) {
    int i = (blockIdx.x * blockDim.x + threadIdx.x) * 4;   // 16384 elems
    float4 v = *(const float4*)(W + i);
    uint4 h, l;
    split_tf32(v.x, h.x, l.x);
    split_tf32(v.y, h.y, l.y);
    split_tf32(v.z, h.z, l.z);
    split_tf32(v.w, h.w, l.w);
    *(uint4*)&g_wh[layer][i] = h;
    *(uint4*)&g_wl[layer][i] = l;
}

__global__ void split_x_kernel(const float* __restrict__ X, int g) {
    size_t i = ((size_t)blockIdx.x * blockDim.x + threadIdx.x) * 4;
    if (i >= (size_t)NN * 128) return;
    float4 v = *(const float4*)(X + i);
    uint4 h, l;
    split_tf32(v.x, h.x, l.x);
    split_tf32(v.y, h.y, l.y);
    split_tf32(v.z, h.z, l.z);
    split_tf32(v.w, h.w, l.w);
    *(uint4*)&g_xh[g][i] = h;
    *(uint4*)&g_xl[g][i] = l;
}

// ---------------- CSR build ----------------
__global__ void hist_kernel(const int* __restrict__ ei, int g) {
    int i = blockIdx.x * blockDim.x + threadIdx.x;
    if (i < EE) atomicAdd(&g_counts[g][ei[EE + i]], 1);
}

__global__ void scan_kernel(int g) {
    __shared__ int part[1024];
    const int tid = threadIdx.x;
    const int chunk = (NN + 1023) / 1024;        // 49
    int s = tid * chunk;
    int e = s + chunk; if (e > NN) e = NN; if (s > NN) s = NN;
    int sum = 0;
    for (int i = s; i < e; i++) sum += g_counts[g][i] + 1;
    part[tid] = sum;
    __syncthreads();
    for (int off = 1; off < 1024; off <<= 1) {
        int v = (tid >= off) ? part[tid - off] : 0;
        __syncthreads();
        part[tid] += v;
        __syncthreads();
    }
    int base = tid ? part[tid - 1] : 0;
    for (int i = s; i < e; i++) {
        g_rowstart[g][i] = base;
        g_cursor[g][i] = base;
        base += g_counts[g][i] + 1;
    }
    if (tid == 1023) g_rowstart[g][NN] = part[1023];
}

__global__ void scatter_kernel(const int* __restrict__ ei, int g) {
    int i = blockIdx.x * blockDim.x + threadIdx.x;
    if (i >= TOT) return;
    int src, dst;
    if (i < EE) { src = ei[i]; dst = ei[EE + i]; }
    else        { src = i - EE; dst = src; }
    int p = atomicAdd(&g_cursor[g][dst], 1);
    g_csr[g][p] = src;
}

// ---------------- GEMM: O[M,128] = X[M,128] @ W[128,128]  (3xTF32, pre-split) ----------------
#define XS_STRIDE 20
#define WS_STRIDE 136
__global__ __launch_bounds__(256) void gemm_kernel(const uint32_t* __restrict__ XH,
                                                   const uint32_t* __restrict__ XL,
                                                   const uint32_t* __restrict__ WH,
                                                   const uint32_t* __restrict__ WL,
                                                   float* __restrict__ O) {
    __shared__ uint32_t XsH[128 * XS_STRIDE];
    __shared__ uint32_t XsL[128 * XS_STRIDE];
    __shared__ uint32_t WsH[16 * WS_STRIDE];
    __shared__ uint32_t WsL[16 * WS_STRIDE];

    const int t    = threadIdx.x;
    const int lane = t & 31;
    const int wid  = t >> 5;
    const int warpM = wid >> 1;                  // 0..3
    const int warpN = wid & 1;                   // 0..1
    const int m0 = warpM * 32;
    const int n0 = warpN * 64;
    const int g  = lane >> 2;                    // 0..7
    const int tg = lane & 3;                     // 0..3
    const int row0 = blockIdx.x * 128;

    float acc[2][8][4];
#pragma unroll
    for (int mt = 0; mt < 2; mt++)
#pragma unroll
        for (int nt = 0; nt < 8; nt++)
#pragma unroll
            for (int j = 0; j < 4; j++) acc[mt][nt][j] = 0.f;

    // staging indices (constant across chunks)
    const int rX  = t >> 1;                      // X rows: 0..127
    const int kqX = (t & 1) * 2;                 // X uint4 col base: 0 or 2
    const int krW = t >> 5;                      // W k rows: 0..7 (+8 on q=1)
    const int c4W = t & 31;                      // W uint4 col: 0..31

    for (int kc = 0; kc < 128; kc += 16) {
        __syncthreads();
        // X tile: rows row0..row0+127, k = kc..kc+15 (hi & lo)
#pragma unroll
        for (int q = 0; q < 2; q++) {
            int r = rX, kq = kqX + q;
            int row = row0 + r; if (row >= NN) row = NN - 1;
            *(uint4*)&XsH[r * XS_STRIDE + kq * 4] =
                *(const uint4*)(XH + (size_t)row * 128 + kc + kq * 4);
            *(uint4*)&XsL[r * XS_STRIDE + kq * 4] =
                *(const uint4*)(XL + (size_t)row * 128 + kc + kq * 4);
        }
        // W chunk: k = kc..kc+15, n = 0..127 (hi & lo)
#pragma unroll
        for (int q = 0; q < 2; q++) {
            int kr = krW + q * 8, c4 = c4W;
            *(uint4*)&WsH[kr * WS_STRIDE + c4 * 4] =
                *(const uint4*)(WH + (size_t)(kc + kr) * 128 + c4 * 4);
            *(uint4*)&WsL[kr * WS_STRIDE + c4 * 4] =
                *(const uint4*)(WL + (size_t)(kc + kr) * 128 + c4 * 4);
        }
        __syncthreads();

#pragma unroll
        for (int s = 0; s < 2; s++) {
            const int k0 = s * 8;
            uint32_t ah[2][4], al[2][4];
#pragma unroll
            for (int mt = 0; mt < 2; mt++) {
                int mr = m0 + mt * 16;
                ah[mt][0] = XsH[(mr + g)     * XS_STRIDE + k0 + tg];
                ah[mt][1] = XsH[(mr + g + 8) * XS_STRIDE + k0 + tg];
                ah[mt][2] = XsH[(mr + g)     * XS_STRIDE + k0 + tg + 4];
                ah[mt][3] = XsH[(mr + g + 8) * XS_STRIDE + k0 + tg + 4];
                al[mt][0] = XsL[(mr + g)     * XS_STRIDE + k0 + tg];
                al[mt][1] = XsL[(mr + g + 8) * XS_STRIDE + k0 + tg];
                al[mt][2] = XsL[(mr + g)     * XS_STRIDE + k0 + tg + 4];
                al[mt][3] = XsL[(mr + g + 8) * XS_STRIDE + k0 + tg + 4];
            }
#pragma unroll
            for (int nt = 0; nt < 8; nt++) {
                const int nc = n0 + nt * 8 + g;
                uint32_t bh[2], bl[2];
                bh[0] = WsH[(k0 + tg)     * WS_STRIDE + nc];
                bh[1] = WsH[(k0 + tg + 4) * WS_STRIDE + nc];
                bl[0] = WsL[(k0 + tg)     * WS_STRIDE + nc];
                bl[1] = WsL[(k0 + tg + 4) * WS_STRIDE + nc];
#pragma unroll
                for (int mt = 0; mt < 2; mt++) {
                    mma_tf32(acc[mt][nt], ah[mt], bh);
                    mma_tf32(acc[mt][nt], al[mt], bh);
                    mma_tf32(acc[mt][nt], ah[mt], bl);
                }
            }
        }
    }

#pragma unroll
    for (int mt = 0; mt < 2; mt++) {
        int rowA = row0 + m0 + mt * 16 + g;
        int rowB = rowA + 8;
#pragma unroll
        for (int nt = 0; nt < 8; nt++) {
            int col = n0 + nt * 8 + tg * 2;
            if (rowA < NN)
                *(float2*)(O + (size_t)rowA * 128 + col) =
                    make_float2(acc[mt][nt][0], acc[mt][nt][1]);
            if (rowB < NN)
                *(float2*)(O + (size_t)rowB * 128 + col) =
                    make_float2(acc[mt][nt][2], acc[mt][nt][3]);
        }
    }
}

// ---------------- alpha_src / alpha_dst ----------------
__global__ void alpha_kernel(const float* __restrict__ H, int g,
                             const float* __restrict__ a_src,
                             const float* __restrict__ a_dst) {
    int w = (blockIdx.x * blockDim.x + threadIdx.x) >> 5;
    if (w >= NN) return;
    int lane = threadIdx.x & 31;
    int head = lane >> 4;
    int d0 = (lane & 15) * 4;
    float4 v = *(const float4*)(H + (size_t)w * 128 + lane * 4);
    const float* as = a_src + head * 64 + d0;
    const float* ad = a_dst + head * 64 + d0;
    float s = v.x * as[0] + v.y * as[1] + v.z * as[2] + v.w * as[3];
    float d = v.x * ad[0] + v.y * ad[1] + v.z * ad[2] + v.w * ad[3];
#pragma unroll
    for (int off = 8; off >= 1; off >>= 1) {
        s += __shfl_xor_sync(0xffffffffu, s, off);
        d += __shfl_xor_sync(0xffffffffu, d, off);
    }
    if ((lane & 15) == 0) {
        g_as[g][w * 2 + head] = s;
        g_ad[g][w * 2 + head] = d;
    }
}

// ---------------- softmax aggregation: one warp per destination node ----------------
// If split_out != 0, also writes tf32 hi/lo of the (post-relu) result into g_xh/g_xl[g].
__global__ void agg_kernel(const float* __restrict__ H, int g,
                           const float* __restrict__ bias,
                           float* __restrict__ out, int do_relu, int split_out) {
    int w = (blockIdx.x * blockDim.x + threadIdx.x) >> 5;
    if (w >= NN) return;
    int lane = threadIdx.x & 31;
    int beg = g_rowstart[g][w], end = g_rowstart[g][w + 1];
    float ad0 = g_ad[g][w * 2], ad1 = g_ad[g][w * 2 + 1];

    float m0 = -1e30f, m1 = -1e30f, s0 = 0.f, s1 = 0.f;
    for (int e = beg + lane; e < end; e += 32) {
        int src = g_csr[g][e];
        float2 av = *(const float2*)&g_as[g][src * 2];
        float e0 = lrelu(av.x + ad0, 0.2f);
        float e1 = lrelu(av.y + ad1, 0.2f);
        if (e0 > m0) { s0 = s0 * __expf(m0 - e0) + 1.f; m0 = e0; } else s0 += __expf(e0 - m0);
        if (e1 > m1) { s1 = s1 * __expf(m1 - e1) + 1.f; m1 = e1; } else s1 += __expf(e1 - m1);
    }
#pragma unroll
    for (int off = 16; off >= 1; off >>= 1) {
        float mo = __shfl_xor_sync(0xffffffffu, m0, off);
        float so = __shfl_xor_sync(0xffffffffu, s0, off);
        float mn = fmaxf(m0, mo);
        s0 = s0 * __expf(m0 - mn) + so * __expf(mo - mn); m0 = mn;
        mo = __shfl_xor_sync(0xffffffffu, m1, off);
        so = __shfl_xor_sync(0xffffffffu, s1, off);
        mn = fmaxf(m1, mo);
        s1 = s1 * __expf(m1 - mn) + so * __expf(mo - mn); m1 = mn;
    }
    float inv0 = 1.f / s0;
    float inv1 = 1.f / s1;

    const int col  = lane * 4;
    const int head = lane >> 4;
    float4 acc = make_float4(0.f, 0.f, 0.f, 0.f);

    for (int base = beg; base < end; base += 32) {
        int cnt = end - base; if (cnt > 32) cnt = 32;
        int   sidx = 0; float aa0 = 0.f, aa1 = 0.f;
        if (lane < cnt) {
            sidx = g_csr[g][base + lane];
            float2 av = *(const float2*)&g_as[g][sidx * 2];
            float e0 = lrelu(av.x + ad0, 0.2f);
            float e1 = lrelu(av.y + ad1, 0.2f);
            aa0 = __expf(e0 - m0) * inv0;
            aa1 = __expf(e1 - m1) * inv1;
        }
#pragma unroll 4
        for (int j = 0; j < cnt; j++) {
            int   sj  = __shfl_sync(0xffffffffu, sidx, j);
            float a0j = __shfl_sync(0xffffffffu, aa0, j);
            float a1j = __shfl_sync(0xffffffffu, aa1, j);
            float aj  = head ? a1j : a0j;
            float4 v = *(const float4*)(H + (size_t)sj * 128 + col);
            acc.x += aj * v.x; acc.y += aj * v.y; acc.z += aj * v.z; acc.w += aj * v.w;
        }
    }

    float4 bv = *(const float4*)(bias + col);
    float4 r = make_float4(acc.x + bv.x, acc.y + bv.y, acc.z + bv.z, acc.w + bv.w);
    if (do_relu) {
        r.x = fmaxf(r.x, 0.f); r.y = fmaxf(r.y, 0.f);
        r.z = fmaxf(r.z, 0.f); r.w = fmaxf(r.w, 0.f);
    }
    *(float4*)(out + (size_t)w * 128 + col) = r;
    if (split_out) {
        uint4 h, l;
        split_tf32(r.x, h.x, l.x);
        split_tf32(r.y, h.y, l.y);
        split_tf32(r.z, h.z, l.z);
        split_tf32(r.w, h.w, l.w);
        *(uint4*)&g_xh[g][(size_t)w * 128 + col] = h;
        *(uint4*)&g_xl[g][(size_t)w * 128 + col] = l;
    }
}

// ---------------- tprob = leaky_relu(xZ2 @ Wp + bp, 0.01) ----------------
__global__ void tprob_kernel(const float* __restrict__ Z, const float* __restrict__ Wp,
                             const float* __restrict__ bp, float* __restrict__ out) {
    int w = (blockIdx.x * blockDim.x + threadIdx.x) >> 5;
    if (w >= NN) return;
    int lane = threadIdx.x & 31;
    int col = lane * 4;
    float4 v  = *(const float4*)(Z + (size_t)w * 128 + col);
    float4 p0 = *(const float4*)(Wp + col * 2);
    float4 p1 = *(const float4*)(Wp + col * 2 + 4);
    float a0 = v.x * p0.x + v.y * p0.z + v.z * p1.x + v.w * p1.z;
    float a1 = v.x * p0.y + v.y * p0.w + v.z * p1.y + v.w * p1.w;
#pragma unroll
    for (int off = 16; off >= 1; off >>= 1) {
        a0 += __shfl_xor_sync(0xffffffffu, a0, off);
        a1 += __shfl_xor_sync(0xffffffffu, a1, off);
    }
    if (lane == 0) {
        float o0 = lrelu(a0 + bp[0], 0.01f);
        float o1 = lrelu(a1 + bp[1], 0.01f);
        *(float2*)(out + (size_t)w * 2) = make_float2(o0, o1);
    }
}

// ---------------- fused y heads ----------------
__global__ void heads_kernel(const float* __restrict__ Z0, const float* __restrict__ Z1,
                             const int* __restrict__ treat, const int* __restrict__ control,
                             const float* __restrict__ WyS, const float* __restrict__ byS,
                             const float* __restrict__ Wy1, const float* __restrict__ by1,
                             const float* __restrict__ Wy0, const float* __restrict__ by0,
                             float* __restrict__ out, int nt, int nc) {
    __shared__ float Ws[128 * 64];
    __shared__ float bs[64];
    __shared__ float wy[64];
    __shared__ float byv;

    const int y = blockIdx.y;
    const float* Z   = (y == 0 || y == 2) ? Z0 : Z1;
    const int*   idx = (y < 2) ? treat : control;
    const float* Wy  = (y == 0 || y == 3) ? Wy1 : Wy0;
    const float* by  = (y == 0 || y == 3) ? by1 : by0;
    const int    cnt = (y < 2) ? nt : nc;
    float* yout = out + (y == 0 ? 0 : y == 1 ? nt : y == 2 ? 2 * nt : 2 * nt + nc);

    const int t = threadIdx.x;                   // 256 threads = 8 warps
#pragma unroll
    for (int i = 0; i < 32; i++) Ws[t + i * 256] = WyS[t + i * 256];
    if (t < 64) { bs[t] = byS[t]; wy[t] = Wy[t]; }
    if (t == 0) byv = by[0];
    __syncthreads();

    const int warp = t >> 5, lane = t & 31;
    for (int i = blockIdx.x * 8 + warp; i < cnt; i += gridDim.x * 8) {
        int node = idx[i];
        const float* z = Z + (size_t)node * 128;
        float za = z[lane], zb = z[lane + 32], zc = z[lane + 64], zd = z[lane + 96];
        float s0 = bs[lane], s1 = bs[lane + 32];
#pragma unroll
        for (int k = 0; k < 128; k++) {
            float src = (k < 32) ? za : (k < 64) ? zb : (k < 96) ? zc : zd;
            float zk = __shfl_sync(0xffffffffu, src, k & 31);
            s0 += zk * Ws[k * 64 + lane];
            s1 += zk * Ws[k * 64 + lane + 32];
        }
        s0 = lrelu(s0, 0.01f);
        s1 = lrelu(s1, 0.01f);
        float p = s0 * wy[lane] + s1 * wy[lane + 32];
#pragma unroll
        for (int off = 16; off >= 1; off >>= 1) p += __shfl_xor_sync(0xffffffffu, p, off);
        if (lane == 0) yout[i] = lrelu(p + byv, 0.01f);
    }
}

// ---------------- launch ----------------
static void build_csr(cudaStream_t s, const int* ei, int g, int* counts_ptr) {
    cudaMemsetAsync(counts_ptr, 0, NN * sizeof(int), s);
    hist_kernel<<<(EE + 255) / 256, 256, 0, s>>>(ei, g);
    scan_kernel<<<1, 1024, 0, s>>>(g);
    scatter_kernel<<<(TOT + 255) / 256, 256, 0, s>>>(ei, g);
}

extern "C" void kernel_launch(void* const* d_in, const int* in_sizes, int n_in,
                              void* d_out, int out_size) {
    const float* x       = (const float*)d_in[0];
    const int*   ei      = (const int*)d_in[1];
    const float* fx      = (const float*)d_in[2];
    const int*   fei     = (const int*)d_in[3];
    const int*   treat   = (const int*)d_in[4];
    const int*   control = (const int*)d_in[5];
    const float* W1      = (const float*)d_in[6];
    const float* as1     = (const float*)d_in[7];
    const float* ad1     = (const float*)d_in[8];
    const float* b1      = (const float*)d_in[9];
    const float* W2      = (const float*)d_in[10];
    const float* as2     = (const float*)d_in[11];
    const float* ad2     = (const float*)d_in[12];
    const float* b2      = (const float*)d_in[13];
    const float* WyS     = (const float*)d_in[14];
    const float* byS     = (const float*)d_in[15];
    const float* Wy1     = (const float*)d_in[16];
    const float* by1     = (const float*)d_in[17];
    const float* Wy0     = (const float*)d_in[18];
    const float* by0     = (const float*)d_in[19];
    const float* Wp      = (const float*)d_in[20];
    const float* bp      = (const float*)d_in[21];
    float* out = (float*)d_out;
    const int nt = in_sizes[4];
    const int nc = in_sizes[5];

    float*    hbase  = nullptr;
    float*    z1     = nullptr;
    int*      counts = nullptr;
    uint32_t* xh     = nullptr;
    uint32_t* xl     = nullptr;
    uint32_t* wh     = nullptr;
    uint32_t* wl     = nullptr;
    cudaGetSymbolAddress((void**)&hbase, g_h);
    cudaGetSymbolAddress((void**)&z1, g_z1);
    cudaGetSymbolAddress((void**)&counts, g_counts);
    cudaGetSymbolAddress((void**)&xh, g_xh);
    cudaGetSymbolAddress((void**)&xl, g_xl);
    cudaGetSymbolAddress((void**)&wh, g_wh);
    cudaGetSymbolAddress((void**)&wl, g_wl);
    float* hA  = hbase;
    float* hB  = hbase + (size_t)NN * 128;
    float* z1a = z1;
    float* z1b = z1 + (size_t)NN * 128;
    int* cntA = counts;
    int* cntB = counts + NN;
    uint32_t* xhA = xh;
    uint32_t* xhB = xh + (size_t)NN * 128;
    uint32_t* xlA = xl;
    uint32_t* xlB = xl + (size_t)NN * 128;
    uint32_t* wh1 = wh;
    uint32_t* wh2 = wh + 128 * 128;
    uint32_t* wl1 = wl;
    uint32_t* wl2 = wl + 128 * 128;

    const size_t OFF_XZ2  = (size_t)2 * nt + (size_t)2 * nc;
    const size_t OFF_XFZ2 = OFF_XZ2 + (size_t)NN * 128;
    const size_t OFF_TP   = OFF_XFZ2 + (size_t)NN * 128;

    static cudaStream_t sB = nullptr;
    static cudaEvent_t evFork = nullptr, evJoin = nullptr;
    if (sB == nullptr) {
        cudaStreamCreateWithFlags(&sB, cudaStreamNonBlocking);
        cudaEventCreateWithFlags(&evFork, cudaEventDisableTiming);
        cudaEventCreateWithFlags(&evJoin, cudaEventDisableTiming);
    }
    cudaStream_t sA = 0;  // legacy default (the captured stream)

    // W splits visible to both streams, then fork
    split_w_kernel<<<16, 256, 0, sA>>>(W1, 0);
    split_w_kernel<<<16, 256, 0, sA>>>(W2, 1);
    cudaEventRecord(evFork, sA);
    cudaStreamWaitEvent(sB, evFork, 0);

    const int SPLIT_BLK = (NN * 128 / 4 + 255) / 256;   // 6250
    const int WARP_BLK  = (NN * 32) / 256;              // 6250

    // ---- real chain on sA ----
    split_x_kernel<<<SPLIT_BLK, 256, 0, sA>>>(x, 0);
    build_csr(sA, ei, 0, cntA);
    gemm_kernel<<<(NN + 127) / 128, 256, 0, sA>>>(xhA, xlA, wh1, wl1, hA);
    alpha_kernel<<<WARP_BLK, 256, 0, sA>>>(hA, 0, as1, ad1);
    agg_kernel<<<WARP_BLK, 256, 0, sA>>>(hA, 0, b1, z1a, 1, 1);   // writes xhA/xlA
    gemm_kernel<<<(NN + 127) / 128, 256, 0, sA>>>(xhA, xlA, wh2, wl2, hA);
    alpha_kernel<<<WARP_BLK, 256, 0, sA>>>(hA, 0, as2, ad2);
    agg_kernel<<<WARP_BLK, 256, 0, sA>>>(hA, 0, b2, out + OFF_XZ2, 0, 0);
    tprob_kernel<<<WARP_BLK, 256, 0, sA>>>(out + OFF_XZ2, Wp, bp, out + OFF_TP);

    // ---- fake chain on sB ----
    split_x_kernel<<<SPLIT_BLK, 256, 0, sB>>>(fx, 1);
    build_csr(sB, fei, 1, cntB);
    gemm_kernel<<<(NN + 127) / 128, 256, 0, sB>>>(xhB, xlB, wh1, wl1, hB);
    alpha_kernel<<<WARP_BLK, 256, 0, sB>>>(hB, 1, as1, ad1);
    agg_kernel<<<WARP_BLK, 256, 0, sB>>>(hB, 1, b1, z1b, 1, 1);   // writes xhB/xlB
    gemm_kernel<<<(NN + 127) / 128, 256, 0, sB>>>(xhB, xlB, wh2, wl2, hB);
    alpha_kernel<<<WARP_BLK, 256, 0, sB>>>(hB, 1, as2, ad2);
    agg_kernel<<<WARP_BLK, 256, 0, sB>>>(hB, 1, b2, out + OFF_XFZ2, 0, 0);

    // join
    cudaEventRecord(evJoin, sB);
    cudaStreamWaitEvent(sA, evJoin, 0);

    heads_kernel<<<dim3(32, 4), 256, 0, sA>>>(out + OFF_XZ2, out + OFF_XFZ2, treat, control,
                                              WyS, byS, Wy1, by1, Wy0, by0, out, nt, nc);
}

// round 9
// speedup vs baseline: 1.1514x; 1.1514x over previous
#include <cuda_runtime.h>
#include <cuda_bf16.h>
#include <cuda_fp16.h>
#include <cstdint>

#define NN 50000
#define EE 800000
#define TOT (EE + NN)

// ---------------- scratch (static device globals; no allocations) ----------------
__device__ __half   g_h16[2][(size_t)NN * 128];  // per-chain GEMM output (fp16, pre-bias)
__device__ float    g_z1[2][(size_t)NN * 128];   // xZ1 (real), xfZ1 (fake)
__device__ uint32_t g_wh[2][128 * 128];          // tf32 hi of W, per layer
__device__ uint32_t g_wl[2][128 * 128];          // tf32 lo of W, per layer
__device__ float    g_as[2][NN * 2];             // alpha_src per node per head
__device__ float    g_ad[2][NN * 2];             // alpha_dst per node per head
__device__ int      g_counts[2][NN];
__device__ int      g_rowstart[2][NN + 1];
__device__ int      g_cursor[2][NN];
__device__ int      g_csr[2][TOT];               // incoming-edge source lists (CSR by dst)

__device__ __forceinline__ float lrelu(float v, float s) { return v > 0.f ? v : s * v; }

__device__ __forceinline__ uint32_t to_tf32(float f) {
    uint32_t r;
    asm("cvt.rna.tf32.f32 %0, %1;" : "=r"(r) : "f"(f));
    return r;
}
__device__ __forceinline__ void split_tf32(float f, uint32_t& h, uint32_t& l) {
    h = to_tf32(f);
    l = to_tf32(f - __uint_as_float(h));
}

__device__ __forceinline__ void mma_tf32(float* d, const uint32_t* a, const uint32_t* b) {
    asm volatile(
        "mma.sync.aligned.m16n8k8.row.col.f32.tf32.tf32.f32 "
        "{%0,%1,%2,%3}, {%4,%5,%6,%7}, {%8,%9}, {%0,%1,%2,%3};\n"
        : "+f"(d[0]), "+f"(d[1]), "+f"(d[2]), "+f"(d[3])
        : "r"(a[0]), "r"(a[1]), "r"(a[2]), "r"(a[3]), "r"(b[0]), "r"(b[1]));
}

// ---------------- W pre-split (W is reused by every block -> split once) ----------------
__global__ void split_w_kernel(const float* __restrict__ W, int layer) {
    int i = (blockIdx.x * blockDim.x + threadIdx.x) * 4;   // 16384 elems
    float4 v = *(const float4*)(W + i);
    uint4 h, l;
    split_tf32(v.x, h.x, l.x);
    split_tf32(v.y, h.y, l.y);
    split_tf32(v.z, h.z, l.z);
    split_tf32(v.w, h.w, l.w);
    *(uint4*)&g_wh[layer][i] = h;
    *(uint4*)&g_wl[layer][i] = l;
}

// ---------------- CSR build ----------------
__global__ void hist_kernel(const int* __restrict__ ei, int g) {
    int i = blockIdx.x * blockDim.x + threadIdx.x;
    if (i < EE) atomicAdd(&g_counts[g][ei[EE + i]], 1);
}

__global__ void scan_kernel(int g) {
    __shared__ int part[1024];
    const int tid = threadIdx.x;
    const int chunk = (NN + 1023) / 1024;        // 49
    int s = tid * chunk;
    int e = s + chunk; if (e > NN) e = NN; if (s > NN) s = NN;
    int sum = 0;
    for (int i = s; i < e; i++) sum += g_counts[g][i] + 1;
    part[tid] = sum;
    __syncthreads();
    for (int off = 1; off < 1024; off <<= 1) {
        int v = (tid >= off) ? part[tid - off] : 0;
        __syncthreads();
        part[tid] += v;
        __syncthreads();
    }
    int base = tid ? part[tid - 1] : 0;
    for (int i = s; i < e; i++) {
        g_rowstart[g][i] = base;
        g_cursor[g][i] = base;
        base += g_counts[g][i] + 1;
    }
    if (tid == 1023) g_rowstart[g][NN] = part[1023];
}

__global__ void scatter_kernel(const int* __restrict__ ei, int g) {
    int i = blockIdx.x * blockDim.x + threadIdx.x;
    if (i >= TOT) return;
    int src, dst;
    if (i < EE) { src = ei[i]; dst = ei[EE + i]; }
    else        { src = i - EE; dst = src; }
    int p = atomicAdd(&g_cursor[g][dst], 1);
    g_csr[g][p] = src;
}

// ---------------- GEMM + fused alpha epilogue ----------------
// O16[M,128](fp16) = X[M,128] @ W[128,128] via 3xTF32; also writes
// g_as/g_ad[g] = per-row per-head dots with a_src/a_dst (fp32 accum).
#define XS_STRIDE 20
#define WS_STRIDE 136
__global__ __launch_bounds__(256) void gemm_kernel(const float* __restrict__ X,
                                                   const uint32_t* __restrict__ WH,
                                                   const uint32_t* __restrict__ WL,
                                                   const float* __restrict__ a_src,
                                                   const float* __restrict__ a_dst,
                                                   int gidx,
                                                   __half* __restrict__ O16) {
    __shared__ uint32_t XsH[128 * XS_STRIDE];
    __shared__ uint32_t XsL[128 * XS_STRIDE];
    __shared__ uint32_t WsH[16 * WS_STRIDE];
    __shared__ uint32_t WsL[16 * WS_STRIDE];
    __shared__ float As[128];
    __shared__ float Ad[128];

    const int t    = threadIdx.x;
    const int lane = t & 31;
    const int wid  = t >> 5;
    const int warpM = wid >> 1;                  // 0..3
    const int warpN = wid & 1;                   // 0..1  (== head)
    const int m0 = warpM * 32;
    const int n0 = warpN * 64;
    const int g  = lane >> 2;                    // 0..7
    const int tg = lane & 3;                     // 0..3
    const int row0 = blockIdx.x * 128;

    if (t < 128) { As[t] = a_src[t]; Ad[t] = a_dst[t]; }

    float acc[2][8][4];
#pragma unroll
    for (int mt = 0; mt < 2; mt++)
#pragma unroll
        for (int nt = 0; nt < 8; nt++)
#pragma unroll
            for (int j = 0; j < 4; j++) acc[mt][nt][j] = 0.f;

    // staging indices (constant across chunks)
    const int rX  = t >> 1;                      // X rows: 0..127
    const int kqX = (t & 1) * 2;                 // X float4 col base: 0 or 2
    const int krW = t >> 5;                      // W k rows: 0..7 (+8 on q=1)
    const int c4W = t & 31;                      // W uint4 col: 0..31

    for (int kc = 0; kc < 128; kc += 16) {
        __syncthreads();
        // X tile: inline tf32 hi/lo split (X used once per block -> no redundancy)
#pragma unroll
        for (int q = 0; q < 2; q++) {
            int r = rX, kq = kqX + q;
            int row = row0 + r; if (row >= NN) row = NN - 1;
            float4 v = *(const float4*)(X + (size_t)row * 128 + kc + kq * 4);
            uint4 h, l;
            split_tf32(v.x, h.x, l.x);
            split_tf32(v.y, h.y, l.y);
            split_tf32(v.z, h.z, l.z);
            split_tf32(v.w, h.w, l.w);
            *(uint4*)&XsH[r * XS_STRIDE + kq * 4] = h;
            *(uint4*)&XsL[r * XS_STRIDE + kq * 4] = l;
        }
        // W chunk: pure copies of pre-split hi/lo
#pragma unroll
        for (int q = 0; q < 2; q++) {
            int kr = krW + q * 8, c4 = c4W;
            *(uint4*)&WsH[kr * WS_STRIDE + c4 * 4] =
                *(const uint4*)(WH + (size_t)(kc + kr) * 128 + c4 * 4);
            *(uint4*)&WsL[kr * WS_STRIDE + c4 * 4] =
                *(const uint4*)(WL + (size_t)(kc + kr) * 128 + c4 * 4);
        }
        __syncthreads();

#pragma unroll
        for (int s = 0; s < 2; s++) {
            const int k0 = s * 8;
            uint32_t ah[2][4], al[2][4];
#pragma unroll
            for (int mt = 0; mt < 2; mt++) {
                int mr = m0 + mt * 16;
                ah[mt][0] = XsH[(mr + g)     * XS_STRIDE + k0 + tg];
                ah[mt][1] = XsH[(mr + g + 8) * XS_STRIDE + k0 + tg];
                ah[mt][2] = XsH[(mr + g)     * XS_STRIDE + k0 + tg + 4];
                ah[mt][3] = XsH[(mr + g + 8) * XS_STRIDE + k0 + tg + 4];
                al[mt][0] = XsL[(mr + g)     * XS_STRIDE + k0 + tg];
                al[mt][1] = XsL[(mr + g + 8) * XS_STRIDE + k0 + tg];
                al[mt][2] = XsL[(mr + g)     * XS_STRIDE + k0 + tg + 4];
                al[mt][3] = XsL[(mr + g + 8) * XS_STRIDE + k0 + tg + 4];
            }
#pragma unroll
            for (int nt = 0; nt < 8; nt++) {
                const int nc = n0 + nt * 8 + g;
                uint32_t bh[2], bl[2];
                bh[0] = WsH[(k0 + tg)     * WS_STRIDE + nc];
                bh[1] = WsH[(k0 + tg + 4) * WS_STRIDE + nc];
                bl[0] = WsL[(k0 + tg)     * WS_STRIDE + nc];
                bl[1] = WsL[(k0 + tg + 4) * WS_STRIDE + nc];
#pragma unroll
                for (int mt = 0; mt < 2; mt++) {
                    mma_tf32(acc[mt][nt], ah[mt], bh);
                    mma_tf32(acc[mt][nt], al[mt], bh);
                    mma_tf32(acc[mt][nt], ah[mt], bl);
                }
            }
        }
    }

    // ---- epilogue: fp16 H store + fused alpha dots ----
#pragma unroll
    for (int mt = 0; mt < 2; mt++) {
        int rowA = row0 + m0 + mt * 16 + g;
        int rowB = rowA + 8;
        float sA = 0.f, dA = 0.f, sB = 0.f, dB = 0.f;
#pragma unroll
        for (int nt = 0; nt < 8; nt++) {
            int col = n0 + nt * 8 + tg * 2;
            float a0s = As[col], a1s = As[col + 1];
            float a0d = Ad[col], a1d = Ad[col + 1];
            sA += acc[mt][nt][0] * a0s + acc[mt][nt][1] * a1s;
            dA += acc[mt][nt][0] * a0d + acc[mt][nt][1] * a1d;
            sB += acc[mt][nt][2] * a0s + acc[mt][nt][3] * a1s;
            dB += acc[mt][nt][2] * a0d + acc[mt][nt][3] * a1d;
            __half2 hA = __floats2half2_rn(acc[mt][nt][0], acc[mt][nt][1]);
            __half2 hB = __floats2half2_rn(acc[mt][nt][2], acc[mt][nt][3]);
            if (rowA < NN) *(__half2*)(O16 + (size_t)rowA * 128 + col) = hA;
            if (rowB < NN) *(__half2*)(O16 + (size_t)rowB * 128 + col) = hB;
        }
        // quad reduce over tg (lanes g*4 .. g*4+3)
#pragma unroll
        for (int off = 1; off <= 2; off <<= 1) {
            sA += __shfl_xor_sync(0xffffffffu, sA, off);
            dA += __shfl_xor_sync(0xffffffffu, dA, off);
            sB += __shfl_xor_sync(0xffffffffu, sB, off);
            dB += __shfl_xor_sync(0xffffffffu, dB, off);
        }
        if (tg == 0) {
            if (rowA < NN) {
                g_as[gidx][rowA * 2 + warpN] = sA;
                g_ad[gidx][rowA * 2 + warpN] = dA;
            }
            if (rowB < NN) {
                g_as[gidx][rowB * 2 + warpN] = sB;
                g_ad[gidx][rowB * 2 + warpN] = dB;
            }
        }
    }
}

// ---------------- softmax aggregation: one warp per destination node ----------------
// Gathers fp16 H rows; softmax stats + accumulation in fp32.
__global__ void agg_kernel(const __half* __restrict__ H16, int g,
                           const float* __restrict__ bias,
                           float* __restrict__ out, int do_relu) {
    int w = (blockIdx.x * blockDim.x + threadIdx.x) >> 5;
    if (w >= NN) return;
    int lane = threadIdx.x & 31;
    int beg = g_rowstart[g][w], end = g_rowstart[g][w + 1];
    float ad0 = g_ad[g][w * 2], ad1 = g_ad[g][w * 2 + 1];

    float m0 = -1e30f, m1 = -1e30f, s0 = 0.f, s1 = 0.f;
    for (int e = beg + lane; e < end; e += 32) {
        int src = g_csr[g][e];
        float2 av = *(const float2*)&g_as[g][src * 2];
        float e0 = lrelu(av.x + ad0, 0.2f);
        float e1 = lrelu(av.y + ad1, 0.2f);
        if (e0 > m0) { s0 = s0 * __expf(m0 - e0) + 1.f; m0 = e0; } else s0 += __expf(e0 - m0);
        if (e1 > m1) { s1 = s1 * __expf(m1 - e1) + 1.f; m1 = e1; } else s1 += __expf(e1 - m1);
    }
#pragma unroll
    for (int off = 16; off >= 1; off >>= 1) {
        float mo = __shfl_xor_sync(0xffffffffu, m0, off);
        float so = __shfl_xor_sync(0xffffffffu, s0, off);
        float mn = fmaxf(m0, mo);
        s0 = s0 * __expf(m0 - mn) + so * __expf(mo - mn); m0 = mn;
        mo = __shfl_xor_sync(0xffffffffu, m1, off);
        so = __shfl_xor_sync(0xffffffffu, s1, off);
        mn = fmaxf(m1, mo);
        s1 = s1 * __expf(m1 - mn) + so * __expf(mo - mn); m1 = mn;
    }
    float inv0 = 1.f / s0;
    float inv1 = 1.f / s1;

    const int col  = lane * 4;
    const int head = lane >> 4;
    float4 acc = make_float4(0.f, 0.f, 0.f, 0.f);

    for (int base = beg; base < end; base += 32) {
        int cnt = end - base; if (cnt > 32) cnt = 32;
        int   sidx = 0; float aa0 = 0.f, aa1 = 0.f;
        if (lane < cnt) {
            sidx = g_csr[g][base + lane];
            float2 av = *(const float2*)&g_as[g][sidx * 2];
            float e0 = lrelu(av.x + ad0, 0.2f);
            float e1 = lrelu(av.y + ad1, 0.2f);
            aa0 = __expf(e0 - m0) * inv0;
            aa1 = __expf(e1 - m1) * inv1;
        }
#pragma unroll 4
        for (int j = 0; j < cnt; j++) {
            int   sj  = __shfl_sync(0xffffffffu, sidx, j);
            float a0j = __shfl_sync(0xffffffffu, aa0, j);
            float a1j = __shfl_sync(0xffffffffu, aa1, j);
            float aj  = head ? a1j : a0j;
            uint2 u = *(const uint2*)(H16 + (size_t)sj * 128 + col);
            float2 f0 = __half22float2(*(__half2*)&u.x);
            float2 f1 = __half22float2(*(__half2*)&u.y);
            acc.x += aj * f0.x; acc.y += aj * f0.y;
            acc.z += aj * f1.x; acc.w += aj * f1.y;
        }
    }

    float4 bv = *(const float4*)(bias + col);
    float4 r = make_float4(acc.x + bv.x, acc.y + bv.y, acc.z + bv.z, acc.w + bv.w);
    if (do_relu) {
        r.x = fmaxf(r.x, 0.f); r.y = fmaxf(r.y, 0.f);
        r.z = fmaxf(r.z, 0.f); r.w = fmaxf(r.w, 0.f);
    }
    *(float4*)(out + (size_t)w * 128 + col) = r;
}

// ---------------- tprob = leaky_relu(xZ2 @ Wp + bp, 0.01) ----------------
__global__ void tprob_kernel(const float* __restrict__ Z, const float* __restrict__ Wp,
                             const float* __restrict__ bp, float* __restrict__ out) {
    int w = (blockIdx.x * blockDim.x + threadIdx.x) >> 5;
    if (w >= NN) return;
    int lane = threadIdx.x & 31;
    int col = lane * 4;
    float4 v  = *(const float4*)(Z + (size_t)w * 128 + col);
    float4 p0 = *(const float4*)(Wp + col * 2);
    float4 p1 = *(const float4*)(Wp + col * 2 + 4);
    float a0 = v.x * p0.x + v.y * p0.z + v.z * p1.x + v.w * p1.z;
    float a1 = v.x * p0.y + v.y * p0.w + v.z * p1.y + v.w * p1.w;
#pragma unroll
    for (int off = 16; off >= 1; off >>= 1) {
        a0 += __shfl_xor_sync(0xffffffffu, a0, off);
        a1 += __shfl_xor_sync(0xffffffffu, a1, off);
    }
    if (lane == 0) {
        float o0 = lrelu(a0 + bp[0], 0.01f);
        float o1 = lrelu(a1 + bp[1], 0.01f);
        *(float2*)(out + (size_t)w * 2) = make_float2(o0, o1);
    }
}

// ---------------- fused y heads ----------------
__global__ void heads_kernel(const float* __restrict__ Z0, const float* __restrict__ Z1,
                             const int* __restrict__ treat, const int* __restrict__ control,
                             const float* __restrict__ WyS, const float* __restrict__ byS,
                             const float* __restrict__ Wy1, const float* __restrict__ by1,
                             const float* __restrict__ Wy0, const float* __restrict__ by0,
                             float* __restrict__ out, int nt, int nc) {
    __shared__ float Ws[128 * 64];
    __shared__ float bs[64];
    __shared__ float wy[64];
    __shared__ float byv;

    const int y = blockIdx.y;
    const float* Z   = (y == 0 || y == 2) ? Z0 : Z1;
    const int*   idx = (y < 2) ? treat : control;
    const float* Wy  = (y == 0 || y == 3) ? Wy1 : Wy0;
    const float* by  = (y == 0 || y == 3) ? by1 : by0;
    const int    cnt = (y < 2) ? nt : nc;
    float* yout = out + (y == 0 ? 0 : y == 1 ? nt : y == 2 ? 2 * nt : 2 * nt + nc);

    const int t = threadIdx.x;                   // 256 threads = 8 warps
#pragma unroll
    for (int i = 0; i < 32; i++) Ws[t + i * 256] = WyS[t + i * 256];
    if (t < 64) { bs[t] = byS[t]; wy[t] = Wy[t]; }
    if (t == 0) byv = by[0];
    __syncthreads();

    const int warp = t >> 5, lane = t & 31;
    for (int i = blockIdx.x * 8 + warp; i < cnt; i += gridDim.x * 8) {
        int node = idx[i];
        const float* z = Z + (size_t)node * 128;
        float za = z[lane], zb = z[lane + 32], zc = z[lane + 64], zd = z[lane + 96];
        float s0 = bs[lane], s1 = bs[lane + 32];
#pragma unroll
        for (int k = 0; k < 128; k++) {
            float src = (k < 32) ? za : (k < 64) ? zb : (k < 96) ? zc : zd;
            float zk = __shfl_sync(0xffffffffu, src, k & 31);
            s0 += zk * Ws[k * 64 + lane];
            s1 += zk * Ws[k * 64 + lane + 32];
        }
        s0 = lrelu(s0, 0.01f);
        s1 = lrelu(s1, 0.01f);
        float p = s0 * wy[lane] + s1 * wy[lane + 32];
#pragma unroll
        for (int off = 16; off >= 1; off >>= 1) p += __shfl_xor_sync(0xffffffffu, p, off);
        if (lane == 0) yout[i] = lrelu(p + byv, 0.01f);
    }
}

// ---------------- launch ----------------
static void build_csr(cudaStream_t s, const int* ei, int g, int* counts_ptr) {
    cudaMemsetAsync(counts_ptr, 0, NN * sizeof(int), s);
    hist_kernel<<<(EE + 255) / 256, 256, 0, s>>>(ei, g);
    scan_kernel<<<1, 1024, 0, s>>>(g);
    scatter_kernel<<<(TOT + 255) / 256, 256, 0, s>>>(ei, g);
}

extern "C" void kernel_launch(void* const* d_in, const int* in_sizes, int n_in,
                              void* d_out, int out_size) {
    const float* x       = (const float*)d_in[0];
    const int*   ei      = (const int*)d_in[1];
    const float* fx      = (const float*)d_in[2];
    const int*   fei     = (const int*)d_in[3];
    const int*   treat   = (const int*)d_in[4];
    const int*   control = (const int*)d_in[5];
    const float* W1      = (const float*)d_in[6];
    const float* as1     = (const float*)d_in[7];
    const float* ad1     = (const float*)d_in[8];
    const float* b1      = (const float*)d_in[9];
    const float* W2      = (const float*)d_in[10];
    const float* as2     = (const float*)d_in[11];
    const float* ad2     = (const float*)d_in[12];
    const float* b2      = (const float*)d_in[13];
    const float* WyS     = (const float*)d_in[14];
    const float* byS     = (const float*)d_in[15];
    const float* Wy1     = (const float*)d_in[16];
    const float* by1     = (const float*)d_in[17];
    const float* Wy0     = (const float*)d_in[18];
    const float* by0     = (const float*)d_in[19];
    const float* Wp      = (const float*)d_in[20];
    const float* bp      = (const float*)d_in[21];
    float* out = (float*)d_out;
    const int nt = in_sizes[4];
    const int nc = in_sizes[5];

    __half*   h16    = nullptr;
    float*    z1     = nullptr;
    int*      counts = nullptr;
    uint32_t* wh     = nullptr;
    uint32_t* wl     = nullptr;
    cudaGetSymbolAddress((void**)&h16, g_h16);
    cudaGetSymbolAddress((void**)&z1, g_z1);
    cudaGetSymbolAddress((void**)&counts, g_counts);
    cudaGetSymbolAddress((void**)&wh, g_wh);
    cudaGetSymbolAddress((void**)&wl, g_wl);
    __half* hA = h16;
    __half* hB = h16 + (size_t)NN * 128;
    float* z1a = z1;
    float* z1b = z1 + (size_t)NN * 128;
    int* cntA = counts;
    int* cntB = counts + NN;
    uint32_t* wh1 = wh;
    uint32_t* wh2 = wh + 128 * 128;
    uint32_t* wl1 = wl;
    uint32_t* wl2 = wl + 128 * 128;

    const size_t OFF_XZ2  = (size_t)2 * nt + (size_t)2 * nc;
    const size_t OFF_XFZ2 = OFF_XZ2 + (size_t)NN * 128;
    const size_t OFF_TP   = OFF_XFZ2 + (size_t)NN * 128;

    static cudaStream_t sB = nullptr;
    static cudaEvent_t evFork = nullptr, evJoin = nullptr;
    if (sB == nullptr) {
        cudaStreamCreateWithFlags(&sB, cudaStreamNonBlocking);
        cudaEventCreateWithFlags(&evFork, cudaEventDisableTiming);
        cudaEventCreateWithFlags(&evJoin, cudaEventDisableTiming);
    }
    cudaStream_t sA = 0;  // legacy default (the captured stream)

    // W splits visible to both streams, then fork
    split_w_kernel<<<16, 256, 0, sA>>>(W1, 0);
    split_w_kernel<<<16, 256, 0, sA>>>(W2, 1);
    cudaEventRecord(evFork, sA);
    cudaStreamWaitEvent(sB, evFork, 0);

    const int WARP_BLK = (NN * 32) / 256;        // 6250
    const int GEMM_BLK = (NN + 127) / 128;       // 391

    // ---- real chain on sA ----
    build_csr(sA, ei, 0, cntA);
    gemm_kernel<<<GEMM_BLK, 256, 0, sA>>>(x,   wh1, wl1, as1, ad1, 0, hA);
    agg_kernel<<<WARP_BLK, 256, 0, sA>>>(hA, 0, b1, z1a, 1);
    gemm_kernel<<<GEMM_BLK, 256, 0, sA>>>(z1a, wh2, wl2, as2, ad2, 0, hA);
    agg_kernel<<<WARP_BLK, 256, 0, sA>>>(hA, 0, b2, out + OFF_XZ2, 0);
    tprob_kernel<<<WARP_BLK, 256, 0, sA>>>(out + OFF_XZ2, Wp, bp, out + OFF_TP);

    // ---- fake chain on sB ----
    build_csr(sB, fei, 1, cntB);
    gemm_kernel<<<GEMM_BLK, 256, 0, sB>>>(fx,  wh1, wl1, as1, ad1, 1, hB);
    agg_kernel<<<WARP_BLK, 256, 0, sB>>>(hB, 1, b1, z1b, 1);
    gemm_kernel<<<GEMM_BLK, 256, 0, sB>>>(z1b, wh2, wl2, as2, ad2, 1, hB);
    agg_kernel<<<WARP_BLK, 256, 0, sB>>>(hB, 1, b2, out + OFF_XFZ2, 0);

    // join
    cudaEventRecord(evJoin, sB);
    cudaStreamWaitEvent(sA, evJoin, 0);

    heads_kernel<<<dim3(32, 4), 256, 0, sA>>>(out + OFF_XZ2, out + OFF_XFZ2, treat, control,
                                              WyS, byS, Wy1, by1, Wy0, by0, out, nt, nc);
}

// round 10
// speedup vs baseline: 1.3570x; 1.1786x over previous
#include <cuda_runtime.h>
#include <cuda_bf16.h>
#include <cuda_fp16.h>
#include <cstdint>

#define NN 50000
#define EE 800000
#define TOT (EE + NN)
#define NB 196                                  // scan blocks: ceil(50000/256)

// ---------------- scratch (static device globals; no allocations) ----------------
__device__ __half   g_h16[2][(size_t)NN * 128];  // per-chain GEMM output (fp16, pre-bias)
__device__ float    g_z1[2][(size_t)NN * 128];   // xZ1 (real), xfZ1 (fake)
__device__ uint32_t g_wh[2][128 * 128];          // tf32 hi of W, per layer
__device__ uint32_t g_wl[2][128 * 128];          // tf32 lo of W, per layer
__device__ float    g_as[2][NN * 2];             // alpha_src per node per head
__device__ float    g_ad[2][NN * 2];             // alpha_dst per node per head
__device__ int      g_counts[2][NN];
__device__ int      g_part[2][256];              // scan partials / offsets
__device__ int      g_rowstart[2][NN + 1];
__device__ int      g_cursor[2][NN];
__device__ int      g_csr[2][TOT];               // incoming-edge source lists (CSR by dst)

__device__ __forceinline__ float lrelu(float v, float s) { return v > 0.f ? v : s * v; }

__device__ __forceinline__ uint32_t to_tf32(float f) {
    uint32_t r;
    asm("cvt.rna.tf32.f32 %0, %1;" : "=r"(r) : "f"(f));
    return r;
}
__device__ __forceinline__ void split_tf32(float f, uint32_t& h, uint32_t& l) {
    h = to_tf32(f);
    l = to_tf32(f - __uint_as_float(h));
}

__device__ __forceinline__ void mma_tf32(float* d, const uint32_t* a, const uint32_t* b) {
    asm volatile(
        "mma.sync.aligned.m16n8k8.row.col.f32.tf32.tf32.f32 "
        "{%0,%1,%2,%3}, {%4,%5,%6,%7}, {%8,%9}, {%0,%1,%2,%3};\n"
        : "+f"(d[0]), "+f"(d[1]), "+f"(d[2]), "+f"(d[3])
        : "r"(a[0]), "r"(a[1]), "r"(a[2]), "r"(a[3]), "r"(b[0]), "r"(b[1]));
}

// ---------------- W pre-split (W is reused by every block -> split once) ----------------
__global__ void split_w_kernel(const float* __restrict__ W, int layer) {
    int i = (blockIdx.x * blockDim.x + threadIdx.x) * 4;   // 16384 elems
    float4 v = *(const float4*)(W + i);
    uint4 h, l;
    split_tf32(v.x, h.x, l.x);
    split_tf32(v.y, h.y, l.y);
    split_tf32(v.z, h.z, l.z);
    split_tf32(v.w, h.w, l.w);
    *(uint4*)&g_wh[layer][i] = h;
    *(uint4*)&g_wl[layer][i] = l;
}

// ---------------- CSR build ----------------
__global__ void hist_kernel(const int* __restrict__ ei, int g) {
    int i = blockIdx.x * blockDim.x + threadIdx.x;
    if (i < EE) atomicAdd(&g_counts[g][ei[EE + i]], 1);
}

// scan stage 1: per-block sums of counts[i]+1
__global__ void partial_kernel(int g) {
    __shared__ int sh[256];
    const int t = threadIdx.x;
    int i = blockIdx.x * 256 + t;
    int v = (i < NN) ? g_counts[g][i] + 1 : 0;
    sh[t] = v;
    __syncthreads();
#pragma unroll
    for (int off = 128; off >= 1; off >>= 1) {
        if (t < off) sh[t] += sh[t + off];
        __syncthreads();
    }
    if (t == 0) g_part[g][blockIdx.x] = sh[0];
}

// scan stage 2: exclusive scan of NB partials; writes rowstart[NN]
__global__ void scan_partials_kernel(int g) {
    __shared__ int sh[256];
    const int t = threadIdx.x;
    int v = (t < NB) ? g_part[g][t] : 0;
    sh[t] = v;
    __syncthreads();
#pragma unroll
    for (int off = 1; off < 256; off <<= 1) {
        int u = (t >= off) ? sh[t - off] : 0;
        __syncthreads();
        sh[t] += u;
        __syncthreads();
    }
    if (t < NB) g_part[g][t] = sh[t] - v;        // exclusive offset
    if (t == NB - 1) g_rowstart[g][NN] = sh[t];  // total
}

// scan stage 3: intra-block scan + block offset -> rowstart/cursor
__global__ void rowstart_kernel(int g) {
    __shared__ int sh[256];
    const int t = threadIdx.x;
    int i = blockIdx.x * 256 + t;
    int v = (i < NN) ? g_counts[g][i] + 1 : 0;
    sh[t] = v;
    __syncthreads();
#pragma unroll
    for (int off = 1; off < 256; off <<= 1) {
        int u = (t >= off) ? sh[t - off] : 0;
        __syncthreads();
        sh[t] += u;
        __syncthreads();
    }
    if (i < NN) {
        int r = g_part[g][blockIdx.x] + sh[t] - v;
        g_rowstart[g][i] = r;
        g_cursor[g][i] = r;
    }
}

__global__ void scatter_kernel(const int* __restrict__ ei, int g) {
    int i = blockIdx.x * blockDim.x + threadIdx.x;
    if (i >= TOT) return;
    int src, dst;
    if (i < EE) { src = ei[i]; dst = ei[EE + i]; }
    else        { src = i - EE; dst = src; }
    int p = atomicAdd(&g_cursor[g][dst], 1);
    g_csr[g][p] = src;
}

// ---------------- GEMM + fused alpha epilogue ----------------
// O16[M,128](fp16) = X[M,128] @ W[128,128] via 3xTF32; also writes
// g_as/g_ad[g] = per-row per-head dots with a_src/a_dst (fp32 accum).
#define XS_STRIDE 20
#define WS_STRIDE 136
__global__ __launch_bounds__(256) void gemm_kernel(const float* __restrict__ X,
                                                   const uint32_t* __restrict__ WH,
                                                   const uint32_t* __restrict__ WL,
                                                   const float* __restrict__ a_src,
                                                   const float* __restrict__ a_dst,
                                                   int gidx,
                                                   __half* __restrict__ O16) {
    __shared__ uint32_t XsH[128 * XS_STRIDE];
    __shared__ uint32_t XsL[128 * XS_STRIDE];
    __shared__ uint32_t WsH[16 * WS_STRIDE];
    __shared__ uint32_t WsL[16 * WS_STRIDE];
    __shared__ float As[128];
    __shared__ float Ad[128];

    const int t    = threadIdx.x;
    const int lane = t & 31;
    const int wid  = t >> 5;
    const int warpM = wid >> 1;                  // 0..3
    const int warpN = wid & 1;                   // 0..1  (== head)
    const int m0 = warpM * 32;
    const int n0 = warpN * 64;
    const int g  = lane >> 2;                    // 0..7
    const int tg = lane & 3;                     // 0..3
    const int row0 = blockIdx.x * 128;

    if (t < 128) { As[t] = a_src[t]; Ad[t] = a_dst[t]; }

    float acc[2][8][4];
#pragma unroll
    for (int mt = 0; mt < 2; mt++)
#pragma unroll
        for (int nt = 0; nt < 8; nt++)
#pragma unroll
            for (int j = 0; j < 4; j++) acc[mt][nt][j] = 0.f;

    // staging indices (constant across chunks)
    const int rX  = t >> 1;                      // X rows: 0..127
    const int kqX = (t & 1) * 2;                 // X float4 col base: 0 or 2
    const int krW = t >> 5;                      // W k rows: 0..7 (+8 on q=1)
    const int c4W = t & 31;                      // W uint4 col: 0..31

    for (int kc = 0; kc < 128; kc += 16) {
        __syncthreads();
        // X tile: inline tf32 hi/lo split (X used once per block -> no redundancy)
#pragma unroll
        for (int q = 0; q < 2; q++) {
            int r = rX, kq = kqX + q;
            int row = row0 + r; if (row >= NN) row = NN - 1;
            float4 v = *(const float4*)(X + (size_t)row * 128 + kc + kq * 4);
            uint4 h, l;
            split_tf32(v.x, h.x, l.x);
            split_tf32(v.y, h.y, l.y);
            split_tf32(v.z, h.z, l.z);
            split_tf32(v.w, h.w, l.w);
            *(uint4*)&XsH[r * XS_STRIDE + kq * 4] = h;
            *(uint4*)&XsL[r * XS_STRIDE + kq * 4] = l;
        }
        // W chunk: pure copies of pre-split hi/lo
#pragma unroll
        for (int q = 0; q < 2; q++) {
            int kr = krW + q * 8, c4 = c4W;
            *(uint4*)&WsH[kr * WS_STRIDE + c4 * 4] =
                *(const uint4*)(WH + (size_t)(kc + kr) * 128 + c4 * 4);
            *(uint4*)&WsL[kr * WS_STRIDE + c4 * 4] =
                *(const uint4*)(WL + (size_t)(kc + kr) * 128 + c4 * 4);
        }
        __syncthreads();

#pragma unroll
        for (int s = 0; s < 2; s++) {
            const int k0 = s * 8;
            uint32_t ah[2][4], al[2][4];
#pragma unroll
            for (int mt = 0; mt < 2; mt++) {
                int mr = m0 + mt * 16;
                ah[mt][0] = XsH[(mr + g)     * XS_STRIDE + k0 + tg];
                ah[mt][1] = XsH[(mr + g + 8) * XS_STRIDE + k0 + tg];
                ah[mt][2] = XsH[(mr + g)     * XS_STRIDE + k0 + tg + 4];
                ah[mt][3] = XsH[(mr + g + 8) * XS_STRIDE + k0 + tg + 4];
                al[mt][0] = XsL[(mr + g)     * XS_STRIDE + k0 + tg];
                al[mt][1] = XsL[(mr + g + 8) * XS_STRIDE + k0 + tg];
                al[mt][2] = XsL[(mr + g)     * XS_STRIDE + k0 + tg + 4];
                al[mt][3] = XsL[(mr + g + 8) * XS_STRIDE + k0 + tg + 4];
            }
#pragma unroll
            for (int nt = 0; nt < 8; nt++) {
                const int nc = n0 + nt * 8 + g;
                uint32_t bh[2], bl[2];
                bh[0] = WsH[(k0 + tg)     * WS_STRIDE + nc];
                bh[1] = WsH[(k0 + tg + 4) * WS_STRIDE + nc];
                bl[0] = WsL[(k0 + tg)     * WS_STRIDE + nc];
                bl[1] = WsL[(k0 + tg + 4) * WS_STRIDE + nc];
#pragma unroll
                for (int mt = 0; mt < 2; mt++) {
                    mma_tf32(acc[mt][nt], ah[mt], bh);
                    mma_tf32(acc[mt][nt], al[mt], bh);
                    mma_tf32(acc[mt][nt], ah[mt], bl);
                }
            }
        }
    }

    // ---- epilogue: fp16 H store + fused alpha dots ----
#pragma unroll
    for (int mt = 0; mt < 2; mt++) {
        int rowA = row0 + m0 + mt * 16 + g;
        int rowB = rowA + 8;
        float sA = 0.f, dA = 0.f, sB = 0.f, dB = 0.f;
#pragma unroll
        for (int nt = 0; nt < 8; nt++) {
            int col = n0 + nt * 8 + tg * 2;
            float a0s = As[col], a1s = As[col + 1];
            float a0d = Ad[col], a1d = Ad[col + 1];
            sA += acc[mt][nt][0] * a0s + acc[mt][nt][1] * a1s;
            dA += acc[mt][nt][0] * a0d + acc[mt][nt][1] * a1d;
            sB += acc[mt][nt][2] * a0s + acc[mt][nt][3] * a1s;
            dB += acc[mt][nt][2] * a0d + acc[mt][nt][3] * a1d;
            __half2 hA = __floats2half2_rn(acc[mt][nt][0], acc[mt][nt][1]);
            __half2 hB = __floats2half2_rn(acc[mt][nt][2], acc[mt][nt][3]);
            if (rowA < NN) *(__half2*)(O16 + (size_t)rowA * 128 + col) = hA;
            if (rowB < NN) *(__half2*)(O16 + (size_t)rowB * 128 + col) = hB;
        }
        // quad reduce over tg (lanes g*4 .. g*4+3)
#pragma unroll
        for (int off = 1; off <= 2; off <<= 1) {
            sA += __shfl_xor_sync(0xffffffffu, sA, off);
            dA += __shfl_xor_sync(0xffffffffu, dA, off);
            sB += __shfl_xor_sync(0xffffffffu, sB, off);
            dB += __shfl_xor_sync(0xffffffffu, dB, off);
        }
        if (tg == 0) {
            if (rowA < NN) {
                g_as[gidx][rowA * 2 + warpN] = sA;
                g_ad[gidx][rowA * 2 + warpN] = dA;
            }
            if (rowB < NN) {
                g_as[gidx][rowB * 2 + warpN] = sB;
                g_ad[gidx][rowB * 2 + warpN] = dB;
            }
        }
    }
}

// ---------------- softmax aggregation: one warp per destination node ----------------
// Gathers fp16 H rows; softmax stats + accumulation in fp32.
__global__ void agg_kernel(const __half* __restrict__ H16, int g,
                           const float* __restrict__ bias,
                           float* __restrict__ out, int do_relu) {
    int w = (blockIdx.x * blockDim.x + threadIdx.x) >> 5;
    if (w >= NN) return;
    int lane = threadIdx.x & 31;
    int beg = g_rowstart[g][w], end = g_rowstart[g][w + 1];
    float ad0 = g_ad[g][w * 2], ad1 = g_ad[g][w * 2 + 1];

    float m0 = -1e30f, m1 = -1e30f, s0 = 0.f, s1 = 0.f;
    for (int e = beg + lane; e < end; e += 32) {
        int src = g_csr[g][e];
        float2 av = *(const float2*)&g_as[g][src * 2];
        float e0 = lrelu(av.x + ad0, 0.2f);
        float e1 = lrelu(av.y + ad1, 0.2f);
        if (e0 > m0) { s0 = s0 * __expf(m0 - e0) + 1.f; m0 = e0; } else s0 += __expf(e0 - m0);
        if (e1 > m1) { s1 = s1 * __expf(m1 - e1) + 1.f; m1 = e1; } else s1 += __expf(e1 - m1);
    }
#pragma unroll
    for (int off = 16; off >= 1; off >>= 1) {
        float mo = __shfl_xor_sync(0xffffffffu, m0, off);
        float so = __shfl_xor_sync(0xffffffffu, s0, off);
        float mn = fmaxf(m0, mo);
        s0 = s0 * __expf(m0 - mn) + so * __expf(mo - mn); m0 = mn;
        mo = __shfl_xor_sync(0xffffffffu, m1, off);
        so = __shfl_xor_sync(0xffffffffu, s1, off);
        mn = fmaxf(m1, mo);
        s1 = s1 * __expf(m1 - mn) + so * __expf(mo - mn); m1 = mn;
    }
    float inv0 = 1.f / s0;
    float inv1 = 1.f / s1;

    const int col  = lane * 4;
    const int head = lane >> 4;
    float4 acc = make_float4(0.f, 0.f, 0.f, 0.f);

    for (int base = beg; base < end; base += 32) {
        int cnt = end - base; if (cnt > 32) cnt = 32;
        int   sidx = 0; float aa0 = 0.f, aa1 = 0.f;
        if (lane < cnt) {
            sidx = g_csr[g][base + lane];
            float2 av = *(const float2*)&g_as[g][sidx * 2];
            float e0 = lrelu(av.x + ad0, 0.2f);
            float e1 = lrelu(av.y + ad1, 0.2f);
            aa0 = __expf(e0 - m0) * inv0;
            aa1 = __expf(e1 - m1) * inv1;
        }
#pragma unroll 4
        for (int j = 0; j < cnt; j++) {
            int   sj  = __shfl_sync(0xffffffffu, sidx, j);
            float a0j = __shfl_sync(0xffffffffu, aa0, j);
            float a1j = __shfl_sync(0xffffffffu, aa1, j);
            float aj  = head ? a1j : a0j;
            uint2 u = *(const uint2*)(H16 + (size_t)sj * 128 + col);
            float2 f0 = __half22float2(*(__half2*)&u.x);
            float2 f1 = __half22float2(*(__half2*)&u.y);
            acc.x += aj * f0.x; acc.y += aj * f0.y;
            acc.z += aj * f1.x; acc.w += aj * f1.y;
        }
    }

    float4 bv = *(const float4*)(bias + col);
    float4 r = make_float4(acc.x + bv.x, acc.y + bv.y, acc.z + bv.z, acc.w + bv.w);
    if (do_relu) {
        r.x = fmaxf(r.x, 0.f); r.y = fmaxf(r.y, 0.f);
        r.z = fmaxf(r.z, 0.f); r.w = fmaxf(r.w, 0.f);
    }
    *(float4*)(out + (size_t)w * 128 + col) = r;
}

// ---------------- tprob = leaky_relu(xZ2 @ Wp + bp, 0.01) ----------------
__global__ void tprob_kernel(const float* __restrict__ Z, const float* __restrict__ Wp,
                             const float* __restrict__ bp, float* __restrict__ out) {
    int w = (blockIdx.x * blockDim.x + threadIdx.x) >> 5;
    if (w >= NN) return;
    int lane = threadIdx.x & 31;
    int col = lane * 4;
    float4 v  = *(const float4*)(Z + (size_t)w * 128 + col);
    float4 p0 = *(const float4*)(Wp + col * 2);
    float4 p1 = *(const float4*)(Wp + col * 2 + 4);
    float a0 = v.x * p0.x + v.y * p0.z + v.z * p1.x + v.w * p1.z;
    float a1 = v.x * p0.y + v.y * p0.w + v.z * p1.y + v.w * p1.w;
#pragma unroll
    for (int off = 16; off >= 1; off >>= 1) {
        a0 += __shfl_xor_sync(0xffffffffu, a0, off);
        a1 += __shfl_xor_sync(0xffffffffu, a1, off);
    }
    if (lane == 0) {
        float o0 = lrelu(a0 + bp[0], 0.01f);
        float o1 = lrelu(a1 + bp[1], 0.01f);
        *(float2*)(out + (size_t)w * 2) = make_float2(o0, o1);
    }
}

// ---------------- fused y heads ----------------
__global__ void heads_kernel(const float* __restrict__ Z0, const float* __restrict__ Z1,
                             const int* __restrict__ treat, const int* __restrict__ control,
                             const float* __restrict__ WyS, const float* __restrict__ byS,
                             const float* __restrict__ Wy1, const float* __restrict__ by1,
                             const float* __restrict__ Wy0, const float* __restrict__ by0,
                             float* __restrict__ out, int nt, int nc) {
    __shared__ float Ws[128 * 64];
    __shared__ float bs[64];
    __shared__ float wy[64];
    __shared__ float byv;

    const int y = blockIdx.y;
    const float* Z   = (y == 0 || y == 2) ? Z0 : Z1;
    const int*   idx = (y < 2) ? treat : control;
    const float* Wy  = (y == 0 || y == 3) ? Wy1 : Wy0;
    const float* by  = (y == 0 || y == 3) ? by1 : by0;
    const int    cnt = (y < 2) ? nt : nc;
    float* yout = out + (y == 0 ? 0 : y == 1 ? nt : y == 2 ? 2 * nt : 2 * nt + nc);

    const int t = threadIdx.x;                   // 256 threads = 8 warps
#pragma unroll
    for (int i = 0; i < 32; i++) Ws[t + i * 256] = WyS[t + i * 256];
    if (t < 64) { bs[t] = byS[t]; wy[t] = Wy[t]; }
    if (t == 0) byv = by[0];
    __syncthreads();

    const int warp = t >> 5, lane = t & 31;
    for (int i = blockIdx.x * 8 + warp; i < cnt; i += gridDim.x * 8) {
        int node = idx[i];
        const float* z = Z + (size_t)node * 128;
        float za = z[lane], zb = z[lane + 32], zc = z[lane + 64], zd = z[lane + 96];
        float s0 = bs[lane], s1 = bs[lane + 32];
#pragma unroll
        for (int k = 0; k < 128; k++) {
            float src = (k < 32) ? za : (k < 64) ? zb : (k < 96) ? zc : zd;
            float zk = __shfl_sync(0xffffffffu, src, k & 31);
            s0 += zk * Ws[k * 64 + lane];
            s1 += zk * Ws[k * 64 + lane + 32];
        }
        s0 = lrelu(s0, 0.01f);
        s1 = lrelu(s1, 0.01f);
        float p = s0 * wy[lane] + s1 * wy[lane + 32];
#pragma unroll
        for (int off = 16; off >= 1; off >>= 1) p += __shfl_xor_sync(0xffffffffu, p, off);
        if (lane == 0) yout[i] = lrelu(p + byv, 0.01f);
    }
}

// ---------------- launch ----------------
static void build_csr(cudaStream_t s, const int* ei, int g, int* counts_ptr) {
    cudaMemsetAsync(counts_ptr, 0, NN * sizeof(int), s);
    hist_kernel<<<(EE + 255) / 256, 256, 0, s>>>(ei, g);
    partial_kernel<<<NB, 256, 0, s>>>(g);
    scan_partials_kernel<<<1, 256, 0, s>>>(g);
    rowstart_kernel<<<NB, 256, 0, s>>>(g);
    scatter_kernel<<<(TOT + 255) / 256, 256, 0, s>>>(ei, g);
}

extern "C" void kernel_launch(void* const* d_in, const int* in_sizes, int n_in,
                              void* d_out, int out_size) {
    const float* x       = (const float*)d_in[0];
    const int*   ei      = (const int*)d_in[1];
    const float* fx      = (const float*)d_in[2];
    const int*   fei     = (const int*)d_in[3];
    const int*   treat   = (const int*)d_in[4];
    const int*   control = (const int*)d_in[5];
    const float* W1      = (const float*)d_in[6];
    const float* as1     = (const float*)d_in[7];
    const float* ad1     = (const float*)d_in[8];
    const float* b1      = (const float*)d_in[9];
    const float* W2      = (const float*)d_in[10];
    const float* as2     = (const float*)d_in[11];
    const float* ad2     = (const float*)d_in[12];
    const float* b2      = (const float*)d_in[13];
    const float* WyS     = (const float*)d_in[14];
    const float* byS     = (const float*)d_in[15];
    const float* Wy1     = (const float*)d_in[16];
    const float* by1     = (const float*)d_in[17];
    const float* Wy0     = (const float*)d_in[18];
    const float* by0     = (const float*)d_in[19];
    const float* Wp      = (const float*)d_in[20];
    const float* bp      = (const float*)d_in[21];
    float* out = (float*)d_out;
    const int nt = in_sizes[4];
    const int nc = in_sizes[5];

    __half*   h16    = nullptr;
    float*    z1     = nullptr;
    int*      counts = nullptr;
    uint32_t* wh     = nullptr;
    uint32_t* wl     = nullptr;
    cudaGetSymbolAddress((void**)&h16, g_h16);
    cudaGetSymbolAddress((void**)&z1, g_z1);
    cudaGetSymbolAddress((void**)&counts, g_counts);
    cudaGetSymbolAddress((void**)&wh, g_wh);
    cudaGetSymbolAddress((void**)&wl, g_wl);
    __half* hA = h16;
    __half* hB = h16 + (size_t)NN * 128;
    float* z1a = z1;
    float* z1b = z1 + (size_t)NN * 128;
    int* cntA = counts;
    int* cntB = counts + NN;
    uint32_t* wh1 = wh;
    uint32_t* wh2 = wh + 128 * 128;
    uint32_t* wl1 = wl;
    uint32_t* wl2 = wl + 128 * 128;

    const size_t OFF_XZ2  = (size_t)2 * nt + (size_t)2 * nc;
    const size_t OFF_XFZ2 = OFF_XZ2 + (size_t)NN * 128;
    const size_t OFF_TP   = OFF_XFZ2 + (size_t)NN * 128;

    static cudaStream_t sB = nullptr;
    static cudaEvent_t evFork = nullptr, evJoin = nullptr;
    if (sB == nullptr) {
        cudaStreamCreateWithFlags(&sB, cudaStreamNonBlocking);
        cudaEventCreateWithFlags(&evFork, cudaEventDisableTiming);
        cudaEventCreateWithFlags(&evJoin, cudaEventDisableTiming);
    }
    cudaStream_t sA = 0;  // legacy default (the captured stream)

    // W splits visible to both streams, then fork
    split_w_kernel<<<16, 256, 0, sA>>>(W1, 0);
    split_w_kernel<<<16, 256, 0, sA>>>(W2, 1);
    cudaEventRecord(evFork, sA);
    cudaStreamWaitEvent(sB, evFork, 0);

    const int WARP_BLK = (NN * 32) / 256;        // 6250
    const int GEMM_BLK = (NN + 127) / 128;       // 391

    // ---- real chain on sA ----
    build_csr(sA, ei, 0, cntA);
    gemm_kernel<<<GEMM_BLK, 256, 0, sA>>>(x,   wh1, wl1, as1, ad1, 0, hA);
    agg_kernel<<<WARP_BLK, 256, 0, sA>>>(hA, 0, b1, z1a, 1);
    gemm_kernel<<<GEMM_BLK, 256, 0, sA>>>(z1a, wh2, wl2, as2, ad2, 0, hA);
    agg_kernel<<<WARP_BLK, 256, 0, sA>>>(hA, 0, b2, out + OFF_XZ2, 0);
    tprob_kernel<<<WARP_BLK, 256, 0, sA>>>(out + OFF_XZ2, Wp, bp, out + OFF_TP);

    // ---- fake chain on sB ----
    build_csr(sB, fei, 1, cntB);
    gemm_kernel<<<GEMM_BLK, 256, 0, sB>>>(fx,  wh1, wl1, as1, ad1, 1, hB);
    agg_kernel<<<WARP_BLK, 256, 0, sB>>>(hB, 1, b1, z1b, 1);
    gemm_kernel<<<GEMM_BLK, 256, 0, sB>>>(z1b, wh2, wl2, as2, ad2, 1, hB);
    agg_kernel<<<WARP_BLK, 256, 0, sB>>>(hB, 1, b2, out + OFF_XFZ2, 0);

    // join
    cudaEventRecord(evJoin, sB);
    cudaStreamWaitEvent(sA, evJoin, 0);

    heads_kernel<<<dim3(32, 4), 256, 0, sA>>>(out + OFF_XZ2, out + OFF_XFZ2, treat, control,
                                              WyS, byS, Wy1, by1, Wy0, by0, out, nt, nc);
}

// round 11
// speedup vs baseline: 1.3794x; 1.0165x over previous
#include <cuda_runtime.h>
#include <cuda_bf16.h>
#include <cuda_fp16.h>
#include <cstdint>

#define NN 50000
#define EE 800000
#define TOT (EE + NN)
#define NB 196                                  // scan blocks: ceil(50000/256)

// ---------------- scratch (static device globals; no allocations) ----------------
__device__ __half   g_h16[2][(size_t)NN * 128];  // per-chain GEMM output (fp16, pre-bias)
__device__ float    g_z1[2][(size_t)NN * 128];   // xZ1 (real), xfZ1 (fake)
__device__ uint32_t g_wh[2][128 * 128];          // tf32 hi of W, per layer
__device__ uint32_t g_wl[2][128 * 128];          // tf32 lo of W, per layer
__device__ float    g_as[2][NN * 2];             // alpha_src per node per head
__device__ float    g_ad[2][NN * 2];             // alpha_dst per node per head
__device__ int      g_counts[2][NN];
__device__ int      g_part[2][256];              // scan partials / offsets
__device__ int      g_rowstart[2][NN + 1];
__device__ int      g_cursor[2][NN];
__device__ int      g_csr[2][TOT];               // incoming-edge source lists (CSR by dst)

__device__ __forceinline__ float lrelu(float v, float s) { return v > 0.f ? v : s * v; }

__device__ __forceinline__ uint32_t to_tf32(float f) {
    uint32_t r;
    asm("cvt.rna.tf32.f32 %0, %1;" : "=r"(r) : "f"(f));
    return r;
}
__device__ __forceinline__ void split_tf32(float f, uint32_t& h, uint32_t& l) {
    h = to_tf32(f);
    l = to_tf32(f - __uint_as_float(h));
}

__device__ __forceinline__ void mma_tf32(float* d, const uint32_t* a, const uint32_t* b) {
    asm volatile(
        "mma.sync.aligned.m16n8k8.row.col.f32.tf32.tf32.f32 "
        "{%0,%1,%2,%3}, {%4,%5,%6,%7}, {%8,%9}, {%0,%1,%2,%3};\n"
        : "+f"(d[0]), "+f"(d[1]), "+f"(d[2]), "+f"(d[3])
        : "r"(a[0]), "r"(a[1]), "r"(a[2]), "r"(a[3]), "r"(b[0]), "r"(b[1]));
}

// ---------------- W pre-split (W is reused by every block -> split once) ----------------
__global__ void split_w_kernel(const float* __restrict__ W, int layer) {
    int i = (blockIdx.x * blockDim.x + threadIdx.x) * 4;   // 16384 elems
    float4 v = *(const float4*)(W + i);
    uint4 h, l;
    split_tf32(v.x, h.x, l.x);
    split_tf32(v.y, h.y, l.y);
    split_tf32(v.z, h.z, l.z);
    split_tf32(v.w, h.w, l.w);
    *(uint4*)&g_wh[layer][i] = h;
    *(uint4*)&g_wl[layer][i] = l;
}

// ---------------- CSR build ----------------
__global__ void hist_kernel(const int* __restrict__ ei, int g) {
    int i = blockIdx.x * blockDim.x + threadIdx.x;
    if (i < EE) atomicAdd(&g_counts[g][ei[EE + i]], 1);
}

// scan stage 1: per-block sums of counts[i]+1
__global__ void partial_kernel(int g) {
    __shared__ int sh[256];
    const int t = threadIdx.x;
    int i = blockIdx.x * 256 + t;
    int v = (i < NN) ? g_counts[g][i] + 1 : 0;
    sh[t] = v;
    __syncthreads();
#pragma unroll
    for (int off = 128; off >= 1; off >>= 1) {
        if (t < off) sh[t] += sh[t + off];
        __syncthreads();
    }
    if (t == 0) g_part[g][blockIdx.x] = sh[0];
}

// scan stage 2: exclusive scan of NB partials; writes rowstart[NN]
__global__ void scan_partials_kernel(int g) {
    __shared__ int sh[256];
    const int t = threadIdx.x;
    int v = (t < NB) ? g_part[g][t] : 0;
    sh[t] = v;
    __syncthreads();
#pragma unroll
    for (int off = 1; off < 256; off <<= 1) {
        int u = (t >= off) ? sh[t - off] : 0;
        __syncthreads();
        sh[t] += u;
        __syncthreads();
    }
    if (t < NB) g_part[g][t] = sh[t] - v;        // exclusive offset
    if (t == NB - 1) g_rowstart[g][NN] = sh[t];  // total
}

// scan stage 3: intra-block scan + block offset -> rowstart/cursor
__global__ void rowstart_kernel(int g) {
    __shared__ int sh[256];
    const int t = threadIdx.x;
    int i = blockIdx.x * 256 + t;
    int v = (i < NN) ? g_counts[g][i] + 1 : 0;
    sh[t] = v;
    __syncthreads();
#pragma unroll
    for (int off = 1; off < 256; off <<= 1) {
        int u = (t >= off) ? sh[t - off] : 0;
        __syncthreads();
        sh[t] += u;
        __syncthreads();
    }
    if (i < NN) {
        int r = g_part[g][blockIdx.x] + sh[t] - v;
        g_rowstart[g][i] = r;
        g_cursor[g][i] = r;
    }
}

__global__ void scatter_kernel(const int* __restrict__ ei, int g) {
    int i = blockIdx.x * blockDim.x + threadIdx.x;
    if (i >= TOT) return;
    int src, dst;
    if (i < EE) { src = ei[i]; dst = ei[EE + i]; }
    else        { src = i - EE; dst = src; }
    int p = atomicAdd(&g_cursor[g][dst], 1);
    g_csr[g][p] = src;
}

// ---------------- GEMM + fused alpha epilogue ----------------
// O16[M,128](fp16) = X[M,128] @ W[128,128] via 3xTF32; also writes
// g_as/g_ad[g] = per-row per-head dots with a_src/a_dst (fp32 accum).
#define XS_STRIDE 20
#define WS_STRIDE 136
__global__ __launch_bounds__(256) void gemm_kernel(const float* __restrict__ X,
                                                   const uint32_t* __restrict__ WH,
                                                   const uint32_t* __restrict__ WL,
                                                   const float* __restrict__ a_src,
                                                   const float* __restrict__ a_dst,
                                                   int gidx,
                                                   __half* __restrict__ O16) {
    __shared__ uint32_t XsH[128 * XS_STRIDE];
    __shared__ uint32_t XsL[128 * XS_STRIDE];
    __shared__ uint32_t WsH[16 * WS_STRIDE];
    __shared__ uint32_t WsL[16 * WS_STRIDE];
    __shared__ float As[128];
    __shared__ float Ad[128];

    const int t    = threadIdx.x;
    const int lane = t & 31;
    const int wid  = t >> 5;
    const int warpM = wid >> 1;                  // 0..3
    const int warpN = wid & 1;                   // 0..1  (== head)
    const int m0 = warpM * 32;
    const int n0 = warpN * 64;
    const int g  = lane >> 2;                    // 0..7
    const int tg = lane & 3;                     // 0..3
    const int row0 = blockIdx.x * 128;

    if (t < 128) { As[t] = a_src[t]; Ad[t] = a_dst[t]; }

    float acc[2][8][4];
#pragma unroll
    for (int mt = 0; mt < 2; mt++)
#pragma unroll
        for (int nt = 0; nt < 8; nt++)
#pragma unroll
            for (int j = 0; j < 4; j++) acc[mt][nt][j] = 0.f;

    // staging indices (constant across chunks)
    const int rX  = t >> 1;                      // X rows: 0..127
    const int kqX = (t & 1) * 2;                 // X float4 col base: 0 or 2
    const int krW = t >> 5;                      // W k rows: 0..7 (+8 on q=1)
    const int c4W = t & 31;                      // W uint4 col: 0..31

    for (int kc = 0; kc < 128; kc += 16) {
        __syncthreads();
        // X tile: inline tf32 hi/lo split (X used once per block -> no redundancy)
#pragma unroll
        for (int q = 0; q < 2; q++) {
            int r = rX, kq = kqX + q;
            int row = row0 + r; if (row >= NN) row = NN - 1;
            float4 v = *(const float4*)(X + (size_t)row * 128 + kc + kq * 4);
            uint4 h, l;
            split_tf32(v.x, h.x, l.x);
            split_tf32(v.y, h.y, l.y);
            split_tf32(v.z, h.z, l.z);
            split_tf32(v.w, h.w, l.w);
            *(uint4*)&XsH[r * XS_STRIDE + kq * 4] = h;
            *(uint4*)&XsL[r * XS_STRIDE + kq * 4] = l;
        }
        // W chunk: pure copies of pre-split hi/lo
#pragma unroll
        for (int q = 0; q < 2; q++) {
            int kr = krW + q * 8, c4 = c4W;
            *(uint4*)&WsH[kr * WS_STRIDE + c4 * 4] =
                *(const uint4*)(WH + (size_t)(kc + kr) * 128 + c4 * 4);
            *(uint4*)&WsL[kr * WS_STRIDE + c4 * 4] =
                *(const uint4*)(WL + (size_t)(kc + kr) * 128 + c4 * 4);
        }
        __syncthreads();

#pragma unroll
        for (int s = 0; s < 2; s++) {
            const int k0 = s * 8;
            uint32_t ah[2][4], al[2][4];
#pragma unroll
            for (int mt = 0; mt < 2; mt++) {
                int mr = m0 + mt * 16;
                ah[mt][0] = XsH[(mr + g)     * XS_STRIDE + k0 + tg];
                ah[mt][1] = XsH[(mr + g + 8) * XS_STRIDE + k0 + tg];
                ah[mt][2] = XsH[(mr + g)     * XS_STRIDE + k0 + tg + 4];
                ah[mt][3] = XsH[(mr + g + 8) * XS_STRIDE + k0 + tg + 4];
                al[mt][0] = XsL[(mr + g)     * XS_STRIDE + k0 + tg];
                al[mt][1] = XsL[(mr + g + 8) * XS_STRIDE + k0 + tg];
                al[mt][2] = XsL[(mr + g)     * XS_STRIDE + k0 + tg + 4];
                al[mt][3] = XsL[(mr + g + 8) * XS_STRIDE + k0 + tg + 4];
            }
#pragma unroll
            for (int nt = 0; nt < 8; nt++) {
                const int nc = n0 + nt * 8 + g;
                uint32_t bh[2], bl[2];
                bh[0] = WsH[(k0 + tg)     * WS_STRIDE + nc];
                bh[1] = WsH[(k0 + tg + 4) * WS_STRIDE + nc];
                bl[0] = WsL[(k0 + tg)     * WS_STRIDE + nc];
                bl[1] = WsL[(k0 + tg + 4) * WS_STRIDE + nc];
#pragma unroll
                for (int mt = 0; mt < 2; mt++) {
                    mma_tf32(acc[mt][nt], ah[mt], bh);
                    mma_tf32(acc[mt][nt], al[mt], bh);
                    mma_tf32(acc[mt][nt], ah[mt], bl);
                }
            }
        }
    }

    // ---- epilogue: fp16 H store + fused alpha dots ----
#pragma unroll
    for (int mt = 0; mt < 2; mt++) {
        int rowA = row0 + m0 + mt * 16 + g;
        int rowB = rowA + 8;
        float sA = 0.f, dA = 0.f, sB = 0.f, dB = 0.f;
#pragma unroll
        for (int nt = 0; nt < 8; nt++) {
            int col = n0 + nt * 8 + tg * 2;
            float a0s = As[col], a1s = As[col + 1];
            float a0d = Ad[col], a1d = Ad[col + 1];
            sA += acc[mt][nt][0] * a0s + acc[mt][nt][1] * a1s;
            dA += acc[mt][nt][0] * a0d + acc[mt][nt][1] * a1d;
            sB += acc[mt][nt][2] * a0s + acc[mt][nt][3] * a1s;
            dB += acc[mt][nt][2] * a0d + acc[mt][nt][3] * a1d;
            __half2 hA = __floats2half2_rn(acc[mt][nt][0], acc[mt][nt][1]);
            __half2 hB = __floats2half2_rn(acc[mt][nt][2], acc[mt][nt][3]);
            if (rowA < NN) *(__half2*)(O16 + (size_t)rowA * 128 + col) = hA;
            if (rowB < NN) *(__half2*)(O16 + (size_t)rowB * 128 + col) = hB;
        }
        // quad reduce over tg (lanes g*4 .. g*4+3)
#pragma unroll
        for (int off = 1; off <= 2; off <<= 1) {
            sA += __shfl_xor_sync(0xffffffffu, sA, off);
            dA += __shfl_xor_sync(0xffffffffu, dA, off);
            sB += __shfl_xor_sync(0xffffffffu, sB, off);
            dB += __shfl_xor_sync(0xffffffffu, dB, off);
        }
        if (tg == 0) {
            if (rowA < NN) {
                g_as[gidx][rowA * 2 + warpN] = sA;
                g_ad[gidx][rowA * 2 + warpN] = dA;
            }
            if (rowB < NN) {
                g_as[gidx][rowB * 2 + warpN] = sB;
                g_ad[gidx][rowB * 2 + warpN] = dB;
            }
        }
    }
}

// ---------------- softmax aggregation: one warp per destination node ----------------
// Gathers fp16 H rows; softmax stats + accumulation in fp32.
__global__ void agg_kernel(const __half* __restrict__ H16, int g,
                           const float* __restrict__ bias,
                           float* __restrict__ out, int do_relu) {
    int w = (blockIdx.x * blockDim.x + threadIdx.x) >> 5;
    if (w >= NN) return;
    int lane = threadIdx.x & 31;
    int beg = g_rowstart[g][w], end = g_rowstart[g][w + 1];
    float ad0 = g_ad[g][w * 2], ad1 = g_ad[g][w * 2 + 1];

    float m0 = -1e30f, m1 = -1e30f, s0 = 0.f, s1 = 0.f;
    for (int e = beg + lane; e < end; e += 32) {
        int src = g_csr[g][e];
        float2 av = *(const float2*)&g_as[g][src * 2];
        float e0 = lrelu(av.x + ad0, 0.2f);
        float e1 = lrelu(av.y + ad1, 0.2f);
        if (e0 > m0) { s0 = s0 * __expf(m0 - e0) + 1.f; m0 = e0; } else s0 += __expf(e0 - m0);
        if (e1 > m1) { s1 = s1 * __expf(m1 - e1) + 1.f; m1 = e1; } else s1 += __expf(e1 - m1);
    }
#pragma unroll
    for (int off = 16; off >= 1; off >>= 1) {
        float mo = __shfl_xor_sync(0xffffffffu, m0, off);
        float so = __shfl_xor_sync(0xffffffffu, s0, off);
        float mn = fmaxf(m0, mo);
        s0 = s0 * __expf(m0 - mn) + so * __expf(mo - mn); m0 = mn;
        mo = __shfl_xor_sync(0xffffffffu, m1, off);
        so = __shfl_xor_sync(0xffffffffu, s1, off);
        mn = fmaxf(m1, mo);
        s1 = s1 * __expf(m1 - mn) + so * __expf(mo - mn); m1 = mn;
    }
    float inv0 = 1.f / s0;
    float inv1 = 1.f / s1;

    const int col  = lane * 4;
    const int head = lane >> 4;
    float4 acc = make_float4(0.f, 0.f, 0.f, 0.f);

    for (int base = beg; base < end; base += 32) {
        int cnt = end - base; if (cnt > 32) cnt = 32;
        int   sidx = 0; float aa0 = 0.f, aa1 = 0.f;
        if (lane < cnt) {
            sidx = g_csr[g][base + lane];
            float2 av = *(const float2*)&g_as[g][sidx * 2];
            float e0 = lrelu(av.x + ad0, 0.2f);
            float e1 = lrelu(av.y + ad1, 0.2f);
            aa0 = __expf(e0 - m0) * inv0;
            aa1 = __expf(e1 - m1) * inv1;
        }
#pragma unroll 4
        for (int j = 0; j < cnt; j++) {
            int   sj  = __shfl_sync(0xffffffffu, sidx, j);
            float a0j = __shfl_sync(0xffffffffu, aa0, j);
            float a1j = __shfl_sync(0xffffffffu, aa1, j);
            float aj  = head ? a1j : a0j;
            uint2 u = *(const uint2*)(H16 + (size_t)sj * 128 + col);
            float2 f0 = __half22float2(*(__half2*)&u.x);
            float2 f1 = __half22float2(*(__half2*)&u.y);
            acc.x += aj * f0.x; acc.y += aj * f0.y;
            acc.z += aj * f1.x; acc.w += aj * f1.y;
        }
    }

    float4 bv = *(const float4*)(bias + col);
    float4 r = make_float4(acc.x + bv.x, acc.y + bv.y, acc.z + bv.z, acc.w + bv.w);
    if (do_relu) {
        r.x = fmaxf(r.x, 0.f); r.y = fmaxf(r.y, 0.f);
        r.z = fmaxf(r.z, 0.f); r.w = fmaxf(r.w, 0.f);
    }
    *(float4*)(out + (size_t)w * 128 + col) = r;
}

// ---------------- tprob = leaky_relu(xZ2 @ Wp + bp, 0.01) ----------------
__global__ void tprob_kernel(const float* __restrict__ Z, const float* __restrict__ Wp,
                             const float* __restrict__ bp, float* __restrict__ out) {
    int w = (blockIdx.x * blockDim.x + threadIdx.x) >> 5;
    if (w >= NN) return;
    int lane = threadIdx.x & 31;
    int col = lane * 4;
    float4 v  = *(const float4*)(Z + (size_t)w * 128 + col);
    float4 p0 = *(const float4*)(Wp + col * 2);
    float4 p1 = *(const float4*)(Wp + col * 2 + 4);
    float a0 = v.x * p0.x + v.y * p0.z + v.z * p1.x + v.w * p1.z;
    float a1 = v.x * p0.y + v.y * p0.w + v.z * p1.y + v.w * p1.w;
#pragma unroll
    for (int off = 16; off >= 1; off >>= 1) {
        a0 += __shfl_xor_sync(0xffffffffu, a0, off);
        a1 += __shfl_xor_sync(0xffffffffu, a1, off);
    }
    if (lane == 0) {
        float o0 = lrelu(a0 + bp[0], 0.01f);
        float o1 = lrelu(a1 + bp[1], 0.01f);
        *(float2*)(out + (size_t)w * 2) = make_float2(o0, o1);
    }
}

// ---------------- fused y heads ----------------
__global__ void heads_kernel(const float* __restrict__ Z0, const float* __restrict__ Z1,
                             const int* __restrict__ treat, const int* __restrict__ control,
                             const float* __restrict__ WyS, const float* __restrict__ byS,
                             const float* __restrict__ Wy1, const float* __restrict__ by1,
                             const float* __restrict__ Wy0, const float* __restrict__ by0,
                             float* __restrict__ out, int nt, int nc) {
    __shared__ float Ws[128 * 64];
    __shared__ float bs[64];
    __shared__ float wy[64];
    __shared__ float byv;

    const int y = blockIdx.y;
    const float* Z   = (y == 0 || y == 2) ? Z0 : Z1;
    const int*   idx = (y < 2) ? treat : control;
    const float* Wy  = (y == 0 || y == 3) ? Wy1 : Wy0;
    const float* by  = (y == 0 || y == 3) ? by1 : by0;
    const int    cnt = (y < 2) ? nt : nc;
    float* yout = out + (y == 0 ? 0 : y == 1 ? nt : y == 2 ? 2 * nt : 2 * nt + nc);

    const int t = threadIdx.x;                   // 256 threads = 8 warps
#pragma unroll
    for (int i = 0; i < 32; i++) Ws[t + i * 256] = WyS[t + i * 256];
    if (t < 64) { bs[t] = byS[t]; wy[t] = Wy[t]; }
    if (t == 0) byv = by[0];
    __syncthreads();

    const int warp = t >> 5, lane = t & 31;
    for (int i = blockIdx.x * 8 + warp; i < cnt; i += gridDim.x * 8) {
        int node = idx[i];
        const float* z = Z + (size_t)node * 128;
        float za = z[lane], zb = z[lane + 32], zc = z[lane + 64], zd = z[lane + 96];
        float s0 = bs[lane], s1 = bs[lane + 32];
#pragma unroll
        for (int k = 0; k < 128; k++) {
            float src = (k < 32) ? za : (k < 64) ? zb : (k < 96) ? zc : zd;
            float zk = __shfl_sync(0xffffffffu, src, k & 31);
            s0 += zk * Ws[k * 64 + lane];
            s1 += zk * Ws[k * 64 + lane + 32];
        }
        s0 = lrelu(s0, 0.01f);
        s1 = lrelu(s1, 0.01f);
        float p = s0 * wy[lane] + s1 * wy[lane + 32];
#pragma unroll
        for (int off = 16; off >= 1; off >>= 1) p += __shfl_xor_sync(0xffffffffu, p, off);
        if (lane == 0) yout[i] = lrelu(p + byv, 0.01f);
    }
}

// ---------------- launch ----------------
static void build_csr(cudaStream_t s, const int* ei, int g, int* counts_ptr) {
    cudaMemsetAsync(counts_ptr, 0, NN * sizeof(int), s);
    hist_kernel<<<(EE + 255) / 256, 256, 0, s>>>(ei, g);
    partial_kernel<<<NB, 256, 0, s>>>(g);
    scan_partials_kernel<<<1, 256, 0, s>>>(g);
    rowstart_kernel<<<NB, 256, 0, s>>>(g);
    scatter_kernel<<<(TOT + 255) / 256, 256, 0, s>>>(ei, g);
}

extern "C" void kernel_launch(void* const* d_in, const int* in_sizes, int n_in,
                              void* d_out, int out_size) {
    const float* x       = (const float*)d_in[0];
    const int*   ei      = (const int*)d_in[1];
    const float* fx      = (const float*)d_in[2];
    const int*   fei     = (const int*)d_in[3];
    const int*   treat   = (const int*)d_in[4];
    const int*   control = (const int*)d_in[5];
    const float* W1      = (const float*)d_in[6];
    const float* as1     = (const float*)d_in[7];
    const float* ad1     = (const float*)d_in[8];
    const float* b1      = (const float*)d_in[9];
    const float* W2      = (const float*)d_in[10];
    const float* as2     = (const float*)d_in[11];
    const float* ad2     = (const float*)d_in[12];
    const float* b2      = (const float*)d_in[13];
    const float* WyS     = (const float*)d_in[14];
    const float* byS     = (const float*)d_in[15];
    const float* Wy1     = (const float*)d_in[16];
    const float* by1     = (const float*)d_in[17];
    const float* Wy0     = (const float*)d_in[18];
    const float* by0     = (const float*)d_in[19];
    const float* Wp      = (const float*)d_in[20];
    const float* bp      = (const float*)d_in[21];
    float* out = (float*)d_out;
    const int nt = in_sizes[4];
    const int nc = in_sizes[5];

    __half*   h16    = nullptr;
    float*    z1     = nullptr;
    int*      counts = nullptr;
    uint32_t* wh     = nullptr;
    uint32_t* wl     = nullptr;
    cudaGetSymbolAddress((void**)&h16, g_h16);
    cudaGetSymbolAddress((void**)&z1, g_z1);
    cudaGetSymbolAddress((void**)&counts, g_counts);
    cudaGetSymbolAddress((void**)&wh, g_wh);
    cudaGetSymbolAddress((void**)&wl, g_wl);
    __half* hA = h16;
    __half* hB = h16 + (size_t)NN * 128;
    float* z1a = z1;
    float* z1b = z1 + (size_t)NN * 128;
    int* cntA = counts;
    int* cntB = counts + NN;
    uint32_t* wh1 = wh;
    uint32_t* wh2 = wh + 128 * 128;
    uint32_t* wl1 = wl;
    uint32_t* wl2 = wl + 128 * 128;

    const size_t OFF_XZ2  = (size_t)2 * nt + (size_t)2 * nc;
    const size_t OFF_XFZ2 = OFF_XZ2 + (size_t)NN * 128;
    const size_t OFF_TP   = OFF_XFZ2 + (size_t)NN * 128;

    static cudaStream_t sB = nullptr, sC = nullptr, sD = nullptr;
    static cudaEvent_t evFork = nullptr, evJoin = nullptr, evCsrA = nullptr, evCsrB = nullptr;
    if (sB == nullptr) {
        cudaStreamCreateWithFlags(&sB, cudaStreamNonBlocking);
        cudaStreamCreateWithFlags(&sC, cudaStreamNonBlocking);
        cudaStreamCreateWithFlags(&sD, cudaStreamNonBlocking);
        cudaEventCreateWithFlags(&evFork, cudaEventDisableTiming);
        cudaEventCreateWithFlags(&evJoin, cudaEventDisableTiming);
        cudaEventCreateWithFlags(&evCsrA, cudaEventDisableTiming);
        cudaEventCreateWithFlags(&evCsrB, cudaEventDisableTiming);
    }
    cudaStream_t sA = 0;  // legacy default (the captured stream)

    // W splits visible to all streams, then fork
    split_w_kernel<<<16, 256, 0, sA>>>(W1, 0);
    split_w_kernel<<<16, 256, 0, sA>>>(W2, 1);
    cudaEventRecord(evFork, sA);
    cudaStreamWaitEvent(sB, evFork, 0);
    cudaStreamWaitEvent(sC, evFork, 0);
    cudaStreamWaitEvent(sD, evFork, 0);

    const int WARP_BLK = (NN * 32) / 256;        // 6250
    const int GEMM_BLK = (NN + 127) / 128;       // 391

    // ---- CSR builds on side streams (overlap the layer-1 GEMMs) ----
    build_csr(sC, ei, 0, cntA);
    cudaEventRecord(evCsrA, sC);
    build_csr(sD, fei, 1, cntB);
    cudaEventRecord(evCsrB, sD);

    // ---- real chain on sA ----
    gemm_kernel<<<GEMM_BLK, 256, 0, sA>>>(x,   wh1, wl1, as1, ad1, 0, hA);
    cudaStreamWaitEvent(sA, evCsrA, 0);          // agg needs the CSR
    agg_kernel<<<WARP_BLK, 256, 0, sA>>>(hA, 0, b1, z1a, 1);
    gemm_kernel<<<GEMM_BLK, 256, 0, sA>>>(z1a, wh2, wl2, as2, ad2, 0, hA);
    agg_kernel<<<WARP_BLK, 256, 0, sA>>>(hA, 0, b2, out + OFF_XZ2, 0);
    tprob_kernel<<<WARP_BLK, 256, 0, sA>>>(out + OFF_XZ2, Wp, bp, out + OFF_TP);

    // ---- fake chain on sB ----
    gemm_kernel<<<GEMM_BLK, 256, 0, sB>>>(fx,  wh1, wl1, as1, ad1, 1, hB);
    cudaStreamWaitEvent(sB, evCsrB, 0);
    agg_kernel<<<WARP_BLK, 256, 0, sB>>>(hB, 1, b1, z1b, 1);
    gemm_kernel<<<GEMM_BLK, 256, 0, sB>>>(z1b, wh2, wl2, as2, ad2, 1, hB);
    agg_kernel<<<WARP_BLK, 256, 0, sB>>>(hB, 1, b2, out + OFF_XFZ2, 0);

    // join (sB already waited on sD; sA already waited on sC)
    cudaEventRecord(evJoin, sB);
    cudaStreamWaitEvent(sA, evJoin, 0);

    heads_kernel<<<dim3(32, 4), 256, 0, sA>>>(out + OFF_XZ2, out + OFF_XFZ2, treat, control,
                                              WyS, byS, Wy1, by1, Wy0, by0, out, nt, nc);
}

// round 12
// speedup vs baseline: 1.4918x; 1.0815x over previous
#include <cuda_runtime.h>
#include <cuda_bf16.h>
#include <cuda_fp16.h>
#include <cstdint>

#define NN 50000
#define EE 800000
#define TOT (EE + NN)
#define NB 196                                  // scan blocks: ceil(50000/256)

// ---------------- scratch (static device globals; no allocations) ----------------
__device__ __half   g_h16[2][(size_t)NN * 128];  // per-chain GEMM output (fp16, pre-bias)
__device__ float    g_z1[2][(size_t)NN * 128];   // xZ1 (real), xfZ1 (fake)
__device__ uint32_t g_wh[2][64 * 128];           // fp16 hi of 32*W, k-pair-packed half2, per layer
__device__ uint32_t g_wl[2][64 * 128];           // fp16 lo of 32*W
__device__ float    g_as[2][NN * 2];             // alpha_src per node per head
__device__ float    g_ad[2][NN * 2];             // alpha_dst per node per head
__device__ int      g_counts[2][NN];
__device__ int      g_part[2][256];              // scan partials / offsets
__device__ int      g_rowstart[2][NN + 1];
__device__ int      g_cursor[2][NN];
__device__ int      g_csr[2][TOT];               // incoming-edge source lists (CSR by dst)

#define W_SCALE     32.0f
#define W_SCALE_INV 0.03125f

__device__ __forceinline__ float lrelu(float v, float s) { return v > 0.f ? v : s * v; }

// fp16 m16n8k16 MMA, fp32 accumulate
__device__ __forceinline__ void mma_f16(float* d, const uint32_t* a, const uint32_t* b) {
    asm volatile(
        "mma.sync.aligned.m16n8k16.row.col.f32.f16.f16.f32 "
        "{%0,%1,%2,%3}, {%4,%5,%6,%7}, {%8,%9}, {%0,%1,%2,%3};\n"
        : "+f"(d[0]), "+f"(d[1]), "+f"(d[2]), "+f"(d[3])
        : "r"(a[0]), "r"(a[1]), "r"(a[2]), "r"(a[3]), "r"(b[0]), "r"(b[1]));
}

// split f32 pair -> fp16 hi half2 + lo half2
__device__ __forceinline__ void split_h2(float x, float y, uint32_t& h, uint32_t& l) {
    __half2 hh = __floats2half2_rn(x, y);
    float2 b = __half22float2(hh);
    __half2 ll = __floats2half2_rn(x - b.x, y - b.y);
    h = *(uint32_t*)&hh;
    l = *(uint32_t*)&ll;
}

// ---------------- W pre-split: 32*W -> fp16 hi/lo, packed half2 along k ----------------
// Output index [kk*128 + n] = half2(32W[2kk][n], 32W[2kk+1][n])
__global__ void split_w_kernel(const float* __restrict__ W, int layer) {
    int i = blockIdx.x * blockDim.x + threadIdx.x;   // 8192 = 64kk * 128n
    int kk = i >> 7, n = i & 127;
    float w0 = W[(2 * kk) * 128 + n] * W_SCALE;
    float w1 = W[(2 * kk + 1) * 128 + n] * W_SCALE;
    uint32_t h, l;
    split_h2(w0, w1, h, l);
    g_wh[layer][i] = h;
    g_wl[layer][i] = l;
}

// ---------------- CSR build ----------------
__global__ void hist_kernel(const int* __restrict__ ei, int g) {
    int i = blockIdx.x * blockDim.x + threadIdx.x;
    if (i < EE) atomicAdd(&g_counts[g][ei[EE + i]], 1);
}

__global__ void partial_kernel(int g) {
    __shared__ int sh[256];
    const int t = threadIdx.x;
    int i = blockIdx.x * 256 + t;
    int v = (i < NN) ? g_counts[g][i] + 1 : 0;
    sh[t] = v;
    __syncthreads();
#pragma unroll
    for (int off = 128; off >= 1; off >>= 1) {
        if (t < off) sh[t] += sh[t + off];
        __syncthreads();
    }
    if (t == 0) g_part[g][blockIdx.x] = sh[0];
}

__global__ void scan_partials_kernel(int g) {
    __shared__ int sh[256];
    const int t = threadIdx.x;
    int v = (t < NB) ? g_part[g][t] : 0;
    sh[t] = v;
    __syncthreads();
#pragma unroll
    for (int off = 1; off < 256; off <<= 1) {
        int u = (t >= off) ? sh[t - off] : 0;
        __syncthreads();
        sh[t] += u;
        __syncthreads();
    }
    if (t < NB) g_part[g][t] = sh[t] - v;        // exclusive offset
    if (t == NB - 1) g_rowstart[g][NN] = sh[t];  // total
}

__global__ void rowstart_kernel(int g) {
    __shared__ int sh[256];
    const int t = threadIdx.x;
    int i = blockIdx.x * 256 + t;
    int v = (i < NN) ? g_counts[g][i] + 1 : 0;
    sh[t] = v;
    __syncthreads();
#pragma unroll
    for (int off = 1; off < 256; off <<= 1) {
        int u = (t >= off) ? sh[t - off] : 0;
        __syncthreads();
        sh[t] += u;
        __syncthreads();
    }
    if (i < NN) {
        int r = g_part[g][blockIdx.x] + sh[t] - v;
        g_rowstart[g][i] = r;
        g_cursor[g][i] = r;
    }
}

__global__ void scatter_kernel(const int* __restrict__ ei, int g) {
    int i = blockIdx.x * blockDim.x + threadIdx.x;
    if (i >= TOT) return;
    int src, dst;
    if (i < EE) { src = ei[i]; dst = ei[EE + i]; }
    else        { src = i - EE; dst = src; }
    int p = atomicAdd(&g_cursor[g][dst], 1);
    g_csr[g][p] = src;
}

// ---------------- GEMM (fp16 2-split) + fused alpha epilogue ----------------
// H = X @ W. acc = X @ (32W); H = acc/32. O16 stores fp16 H; g_as/g_ad get
// per-row per-head dots (folded 1/32 via scaled As/Ad).
#define XS2 9                                    // X smem stride (half2 units per row)
#define WS2 132                                  // W smem stride (half2 units per kk row)
__global__ __launch_bounds__(256) void gemm_kernel(const float* __restrict__ X,
                                                   const uint32_t* __restrict__ WH,
                                                   const uint32_t* __restrict__ WL,
                                                   const float* __restrict__ a_src,
                                                   const float* __restrict__ a_dst,
                                                   int gidx,
                                                   __half* __restrict__ O16) {
    __shared__ uint32_t XsH[128 * XS2];
    __shared__ uint32_t XsL[128 * XS2];
    __shared__ uint32_t WsH[8 * WS2];
    __shared__ uint32_t WsL[8 * WS2];
    __shared__ float As[128];
    __shared__ float Ad[128];

    const int t    = threadIdx.x;
    const int lane = t & 31;
    const int wid  = t >> 5;
    const int warpM = wid >> 1;                  // 0..3
    const int warpN = wid & 1;                   // 0..1  (== head)
    const int m0 = warpM * 32;
    const int n0 = warpN * 64;
    const int g  = lane >> 2;                    // 0..7
    const int tg = lane & 3;                     // 0..3
    const int row0 = blockIdx.x * 128;

    if (t < 128) { As[t] = a_src[t] * W_SCALE_INV; Ad[t] = a_dst[t] * W_SCALE_INV; }

    float acc[2][8][4];
#pragma unroll
    for (int mt = 0; mt < 2; mt++)
#pragma unroll
        for (int nt = 0; nt < 8; nt++)
#pragma unroll
            for (int j = 0; j < 4; j++) acc[mt][nt][j] = 0.f;

    // staging indices
    const int rX  = t >> 1;                      // X rows: 0..127 (2 threads/row)
    const int kqX = (t & 1) * 2;                 // float4 index base: 0 or 2
    const int kkW = t >> 5;                      // W kk row: 0..7
    const int n4W = t & 31;                      // W uint4 col: 0..31

    for (int kc = 0; kc < 8; kc++) {             // 8 chunks of K=16
        __syncthreads();
        // X tile: load float4, split to fp16 hi/lo half2 pairs
#pragma unroll
        for (int q = 0; q < 2; q++) {
            int kq = kqX + q;                    // 0..3 (float4 within chunk)
            int row = row0 + rX; if (row >= NN) row = NN - 1;
            float4 v = *(const float4*)(X + (size_t)row * 128 + kc * 16 + kq * 4);
            uint32_t h0, l0, h1, l1;
            split_h2(v.x, v.y, h0, l0);
            split_h2(v.z, v.w, h1, l1);
            XsH[rX * XS2 + kq * 2]     = h0;
            XsH[rX * XS2 + kq * 2 + 1] = h1;
            XsL[rX * XS2 + kq * 2]     = l0;
            XsL[rX * XS2 + kq * 2 + 1] = l1;
        }
        // W chunk: pure uint4 copies of pre-split packed half2
        *(uint4*)&WsH[kkW * WS2 + n4W * 4] =
            *(const uint4*)(WH + (kc * 8 + kkW) * 128 + n4W * 4);
        *(uint4*)&WsL[kkW * WS2 + n4W * 4] =
            *(const uint4*)(WL + (kc * 8 + kkW) * 128 + n4W * 4);
        __syncthreads();

        uint32_t ah[2][4], al[2][4];
#pragma unroll
        for (int mt = 0; mt < 2; mt++) {
            int mr = m0 + mt * 16;
            ah[mt][0] = XsH[(mr + g)     * XS2 + tg];
            ah[mt][1] = XsH[(mr + g + 8) * XS2 + tg];
            ah[mt][2] = XsH[(mr + g)     * XS2 + tg + 4];
            ah[mt][3] = XsH[(mr + g + 8) * XS2 + tg + 4];
            al[mt][0] = XsL[(mr + g)     * XS2 + tg];
            al[mt][1] = XsL[(mr + g + 8) * XS2 + tg];
            al[mt][2] = XsL[(mr + g)     * XS2 + tg + 4];
            al[mt][3] = XsL[(mr + g + 8) * XS2 + tg + 4];
        }
#pragma unroll
        for (int nt = 0; nt < 8; nt++) {
            const int nc = n0 + nt * 8 + g;
            uint32_t bh[2], bl[2];
            bh[0] = WsH[tg * WS2 + nc];
            bh[1] = WsH[(tg + 4) * WS2 + nc];
            bl[0] = WsL[tg * WS2 + nc];
            bl[1] = WsL[(tg + 4) * WS2 + nc];
#pragma unroll
            for (int mt = 0; mt < 2; mt++) {
                mma_f16(acc[mt][nt], ah[mt], bh);
                mma_f16(acc[mt][nt], al[mt], bh);
                mma_f16(acc[mt][nt], ah[mt], bl);
            }
        }
    }

    // ---- epilogue: fp16 H store (acc/32) + fused alpha dots (As/Ad pre-scaled) ----
#pragma unroll
    for (int mt = 0; mt < 2; mt++) {
        int rowA = row0 + m0 + mt * 16 + g;
        int rowB = rowA + 8;
        float sA = 0.f, dA = 0.f, sB = 0.f, dB = 0.f;
#pragma unroll
        for (int nt = 0; nt < 8; nt++) {
            int col = n0 + nt * 8 + tg * 2;
            float a0s = As[col], a1s = As[col + 1];
            float a0d = Ad[col], a1d = Ad[col + 1];
            sA += acc[mt][nt][0] * a0s + acc[mt][nt][1] * a1s;
            dA += acc[mt][nt][0] * a0d + acc[mt][nt][1] * a1d;
            sB += acc[mt][nt][2] * a0s + acc[mt][nt][3] * a1s;
            dB += acc[mt][nt][2] * a0d + acc[mt][nt][3] * a1d;
            __half2 hA = __floats2half2_rn(acc[mt][nt][0] * W_SCALE_INV,
                                           acc[mt][nt][1] * W_SCALE_INV);
            __half2 hB = __floats2half2_rn(acc[mt][nt][2] * W_SCALE_INV,
                                           acc[mt][nt][3] * W_SCALE_INV);
            if (rowA < NN) *(__half2*)(O16 + (size_t)rowA * 128 + col) = hA;
            if (rowB < NN) *(__half2*)(O16 + (size_t)rowB * 128 + col) = hB;
        }
#pragma unroll
        for (int off = 1; off <= 2; off <<= 1) {
            sA += __shfl_xor_sync(0xffffffffu, sA, off);
            dA += __shfl_xor_sync(0xffffffffu, dA, off);
            sB += __shfl_xor_sync(0xffffffffu, sB, off);
            dB += __shfl_xor_sync(0xffffffffu, dB, off);
        }
        if (tg == 0) {
            if (rowA < NN) {
                g_as[gidx][rowA * 2 + warpN] = sA;
                g_ad[gidx][rowA * 2 + warpN] = dA;
            }
            if (rowB < NN) {
                g_as[gidx][rowB * 2 + warpN] = sB;
                g_ad[gidx][rowB * 2 + warpN] = dB;
            }
        }
    }
}

// ---------------- softmax aggregation: one warp per destination node ----------------
__global__ void agg_kernel(const __half* __restrict__ H16, int g,
                           const float* __restrict__ bias,
                           float* __restrict__ out, int do_relu) {
    int w = (blockIdx.x * blockDim.x + threadIdx.x) >> 5;
    if (w >= NN) return;
    int lane = threadIdx.x & 31;
    int beg = g_rowstart[g][w], end = g_rowstart[g][w + 1];
    float ad0 = g_ad[g][w * 2], ad1 = g_ad[g][w * 2 + 1];

    float m0 = -1e30f, m1 = -1e30f, s0 = 0.f, s1 = 0.f;
    for (int e = beg + lane; e < end; e += 32) {
        int src = g_csr[g][e];
        float2 av = *(const float2*)&g_as[g][src * 2];
        float e0 = lrelu(av.x + ad0, 0.2f);
        float e1 = lrelu(av.y + ad1, 0.2f);
        if (e0 > m0) { s0 = s0 * __expf(m0 - e0) + 1.f; m0 = e0; } else s0 += __expf(e0 - m0);
        if (e1 > m1) { s1 = s1 * __expf(m1 - e1) + 1.f; m1 = e1; } else s1 += __expf(e1 - m1);
    }
#pragma unroll
    for (int off = 16; off >= 1; off >>= 1) {
        float mo = __shfl_xor_sync(0xffffffffu, m0, off);
        float so = __shfl_xor_sync(0xffffffffu, s0, off);
        float mn = fmaxf(m0, mo);
        s0 = s0 * __expf(m0 - mn) + so * __expf(mo - mn); m0 = mn;
        mo = __shfl_xor_sync(0xffffffffu, m1, off);
        so = __shfl_xor_sync(0xffffffffu, s1, off);
        mn = fmaxf(m1, mo);
        s1 = s1 * __expf(m1 - mn) + so * __expf(mo - mn); m1 = mn;
    }
    float inv0 = 1.f / s0;
    float inv1 = 1.f / s1;

    const int col  = lane * 4;
    const int head = lane >> 4;
    float4 acc = make_float4(0.f, 0.f, 0.f, 0.f);

    for (int base = beg; base < end; base += 32) {
        int cnt = end - base; if (cnt > 32) cnt = 32;
        int   sidx = 0; float aa0 = 0.f, aa1 = 0.f;
        if (lane < cnt) {
            sidx = g_csr[g][base + lane];
            float2 av = *(const float2*)&g_as[g][sidx * 2];
            float e0 = lrelu(av.x + ad0, 0.2f);
            float e1 = lrelu(av.y + ad1, 0.2f);
            aa0 = __expf(e0 - m0) * inv0;
            aa1 = __expf(e1 - m1) * inv1;
        }
#pragma unroll 4
        for (int j = 0; j < cnt; j++) {
            int   sj  = __shfl_sync(0xffffffffu, sidx, j);
            float a0j = __shfl_sync(0xffffffffu, aa0, j);
            float a1j = __shfl_sync(0xffffffffu, aa1, j);
            float aj  = head ? a1j : a0j;
            uint2 u = *(const uint2*)(H16 + (size_t)sj * 128 + col);
            float2 f0 = __half22float2(*(__half2*)&u.x);
            float2 f1 = __half22float2(*(__half2*)&u.y);
            acc.x += aj * f0.x; acc.y += aj * f0.y;
            acc.z += aj * f1.x; acc.w += aj * f1.y;
        }
    }

    float4 bv = *(const float4*)(bias + col);
    float4 r = make_float4(acc.x + bv.x, acc.y + bv.y, acc.z + bv.z, acc.w + bv.w);
    if (do_relu) {
        r.x = fmaxf(r.x, 0.f); r.y = fmaxf(r.y, 0.f);
        r.z = fmaxf(r.z, 0.f); r.w = fmaxf(r.w, 0.f);
    }
    *(float4*)(out + (size_t)w * 128 + col) = r;
}

// ---------------- tprob = leaky_relu(xZ2 @ Wp + bp, 0.01) ----------------
__global__ void tprob_kernel(const float* __restrict__ Z, const float* __restrict__ Wp,
                             const float* __restrict__ bp, float* __restrict__ out) {
    int w = (blockIdx.x * blockDim.x + threadIdx.x) >> 5;
    if (w >= NN) return;
    int lane = threadIdx.x & 31;
    int col = lane * 4;
    float4 v  = *(const float4*)(Z + (size_t)w * 128 + col);
    float4 p0 = *(const float4*)(Wp + col * 2);
    float4 p1 = *(const float4*)(Wp + col * 2 + 4);
    float a0 = v.x * p0.x + v.y * p0.z + v.z * p1.x + v.w * p1.z;
    float a1 = v.x * p0.y + v.y * p0.w + v.z * p1.y + v.w * p1.w;
#pragma unroll
    for (int off = 16; off >= 1; off >>= 1) {
        a0 += __shfl_xor_sync(0xffffffffu, a0, off);
        a1 += __shfl_xor_sync(0xffffffffu, a1, off);
    }
    if (lane == 0) {
        float o0 = lrelu(a0 + bp[0], 0.01f);
        float o1 = lrelu(a1 + bp[1], 0.01f);
        *(float2*)(out + (size_t)w * 2) = make_float2(o0, o1);
    }
}

// ---------------- fused y heads ----------------
__global__ void heads_kernel(const float* __restrict__ Z0, const float* __restrict__ Z1,
                             const int* __restrict__ treat, const int* __restrict__ control,
                             const float* __restrict__ WyS, const float* __restrict__ byS,
                             const float* __restrict__ Wy1, const float* __restrict__ by1,
                             const float* __restrict__ Wy0, const float* __restrict__ by0,
                             float* __restrict__ out, int nt, int nc) {
    __shared__ float Ws[128 * 64];
    __shared__ float bs[64];
    __shared__ float wy[64];
    __shared__ float byv;

    const int y = blockIdx.y;
    const float* Z   = (y == 0 || y == 2) ? Z0 : Z1;
    const int*   idx = (y < 2) ? treat : control;
    const float* Wy  = (y == 0 || y == 3) ? Wy1 : Wy0;
    const float* by  = (y == 0 || y == 3) ? by1 : by0;
    const int    cnt = (y < 2) ? nt : nc;
    float* yout = out + (y == 0 ? 0 : y == 1 ? nt : y == 2 ? 2 * nt : 2 * nt + nc);

    const int t = threadIdx.x;                   // 256 threads = 8 warps
#pragma unroll
    for (int i = 0; i < 32; i++) Ws[t + i * 256] = WyS[t + i * 256];
    if (t < 64) { bs[t] = byS[t]; wy[t] = Wy[t]; }
    if (t == 0) byv = by[0];
    __syncthreads();

    const int warp = t >> 5, lane = t & 31;
    for (int i = blockIdx.x * 8 + warp; i < cnt; i += gridDim.x * 8) {
        int node = idx[i];
        const float* z = Z + (size_t)node * 128;
        float za = z[lane], zb = z[lane + 32], zc = z[lane + 64], zd = z[lane + 96];
        float s0 = bs[lane], s1 = bs[lane + 32];
#pragma unroll
        for (int k = 0; k < 128; k++) {
            float src = (k < 32) ? za : (k < 64) ? zb : (k < 96) ? zc : zd;
            float zk = __shfl_sync(0xffffffffu, src, k & 31);
            s0 += zk * Ws[k * 64 + lane];
            s1 += zk * Ws[k * 64 + lane + 32];
        }
        s0 = lrelu(s0, 0.01f);
        s1 = lrelu(s1, 0.01f);
        float p = s0 * wy[lane] + s1 * wy[lane + 32];
#pragma unroll
        for (int off = 16; off >= 1; off >>= 1) p += __shfl_xor_sync(0xffffffffu, p, off);
        if (lane == 0) yout[i] = lrelu(p + byv, 0.01f);
    }
}

// ---------------- launch ----------------
static void build_csr(cudaStream_t s, const int* ei, int g, int* counts_ptr) {
    cudaMemsetAsync(counts_ptr, 0, NN * sizeof(int), s);
    hist_kernel<<<(EE + 255) / 256, 256, 0, s>>>(ei, g);
    partial_kernel<<<NB, 256, 0, s>>>(g);
    scan_partials_kernel<<<1, 256, 0, s>>>(g);
    rowstart_kernel<<<NB, 256, 0, s>>>(g);
    scatter_kernel<<<(TOT + 255) / 256, 256, 0, s>>>(ei, g);
}

extern "C" void kernel_launch(void* const* d_in, const int* in_sizes, int n_in,
                              void* d_out, int out_size) {
    const float* x       = (const float*)d_in[0];
    const int*   ei      = (const int*)d_in[1];
    const float* fx      = (const float*)d_in[2];
    const int*   fei     = (const int*)d_in[3];
    const int*   treat   = (const int*)d_in[4];
    const int*   control = (const int*)d_in[5];
    const float* W1      = (const float*)d_in[6];
    const float* as1     = (const float*)d_in[7];
    const float* ad1     = (const float*)d_in[8];
    const float* b1      = (const float*)d_in[9];
    const float* W2      = (const float*)d_in[10];
    const float* as2     = (const float*)d_in[11];
    const float* ad2     = (const float*)d_in[12];
    const float* b2      = (const float*)d_in[13];
    const float* WyS     = (const float*)d_in[14];
    const float* byS     = (const float*)d_in[15];
    const float* Wy1     = (const float*)d_in[16];
    const float* by1     = (const float*)d_in[17];
    const float* Wy0     = (const float*)d_in[18];
    const float* by0     = (const float*)d_in[19];
    const float* Wp      = (const float*)d_in[20];
    const float* bp      = (const float*)d_in[21];
    float* out = (float*)d_out;
    const int nt = in_sizes[4];
    const int nc = in_sizes[5];

    __half*   h16    = nullptr;
    float*    z1     = nullptr;
    int*      counts = nullptr;
    uint32_t* wh     = nullptr;
    uint32_t* wl     = nullptr;
    cudaGetSymbolAddress((void**)&h16, g_h16);
    cudaGetSymbolAddress((void**)&z1, g_z1);
    cudaGetSymbolAddress((void**)&counts, g_counts);
    cudaGetSymbolAddress((void**)&wh, g_wh);
    cudaGetSymbolAddress((void**)&wl, g_wl);
    __half* hA = h16;
    __half* hB = h16 + (size_t)NN * 128;
    float* z1a = z1;
    float* z1b = z1 + (size_t)NN * 128;
    int* cntA = counts;
    int* cntB = counts + NN;
    uint32_t* wh1 = wh;
    uint32_t* wh2 = wh + 64 * 128;
    uint32_t* wl1 = wl;
    uint32_t* wl2 = wl + 64 * 128;

    const size_t OFF_XZ2  = (size_t)2 * nt + (size_t)2 * nc;
    const size_t OFF_XFZ2 = OFF_XZ2 + (size_t)NN * 128;
    const size_t OFF_TP   = OFF_XFZ2 + (size_t)NN * 128;

    static cudaStream_t sB = nullptr, sC = nullptr, sD = nullptr;
    static cudaEvent_t evFork = nullptr, evJoin = nullptr, evCsrA = nullptr, evCsrB = nullptr;
    if (sB == nullptr) {
        cudaStreamCreateWithFlags(&sB, cudaStreamNonBlocking);
        cudaStreamCreateWithFlags(&sC, cudaStreamNonBlocking);
        cudaStreamCreateWithFlags(&sD, cudaStreamNonBlocking);
        cudaEventCreateWithFlags(&evFork, cudaEventDisableTiming);
        cudaEventCreateWithFlags(&evJoin, cudaEventDisableTiming);
        cudaEventCreateWithFlags(&evCsrA, cudaEventDisableTiming);
        cudaEventCreateWithFlags(&evCsrB, cudaEventDisableTiming);
    }
    cudaStream_t sA = 0;  // legacy default (the captured stream)

    // W splits visible to all streams, then fork
    split_w_kernel<<<32, 256, 0, sA>>>(W1, 0);
    split_w_kernel<<<32, 256, 0, sA>>>(W2, 1);
    cudaEventRecord(evFork, sA);
    cudaStreamWaitEvent(sB, evFork, 0);
    cudaStreamWaitEvent(sC, evFork, 0);
    cudaStreamWaitEvent(sD, evFork, 0);

    const int WARP_BLK = (NN * 32) / 256;        // 6250
    const int GEMM_BLK = (NN + 127) / 128;       // 391

    // ---- CSR builds on side streams (overlap the layer-1 GEMMs) ----
    build_csr(sC, ei, 0, cntA);
    cudaEventRecord(evCsrA, sC);
    build_csr(sD, fei, 1, cntB);
    cudaEventRecord(evCsrB, sD);

    // ---- real chain on sA ----
    gemm_kernel<<<GEMM_BLK, 256, 0, sA>>>(x,   wh1, wl1, as1, ad1, 0, hA);
    cudaStreamWaitEvent(sA, evCsrA, 0);          // agg needs the CSR
    agg_kernel<<<WARP_BLK, 256, 0, sA>>>(hA, 0, b1, z1a, 1);
    gemm_kernel<<<GEMM_BLK, 256, 0, sA>>>(z1a, wh2, wl2, as2, ad2, 0, hA);
    agg_kernel<<<WARP_BLK, 256, 0, sA>>>(hA, 0, b2, out + OFF_XZ2, 0);
    tprob_kernel<<<WARP_BLK, 256, 0, sA>>>(out + OFF_XZ2, Wp, bp, out + OFF_TP);

    // ---- fake chain on sB ----
    gemm_kernel<<<GEMM_BLK, 256, 0, sB>>>(fx,  wh1, wl1, as1, ad1, 1, hB);
    cudaStreamWaitEvent(sB, evCsrB, 0);
    agg_kernel<<<WARP_BLK, 256, 0, sB>>>(hB, 1, b1, z1b, 1);
    gemm_kernel<<<GEMM_BLK, 256, 0, sB>>>(z1b, wh2, wl2, as2, ad2, 1, hB);
    agg_kernel<<<WARP_BLK, 256, 0, sB>>>(hB, 1, b2, out + OFF_XFZ2, 0);

    // join (sB already waited on sD; sA already waited on sC)
    cudaEventRecord(evJoin, sB);
    cudaStreamWaitEvent(sA, evJoin, 0);

    heads_kernel<<<dim3(32, 4), 256, 0, sA>>>(out + OFF_XZ2, out + OFF_XFZ2, treat, control,
                                              WyS, byS, Wy1, by1, Wy0, by0, out, nt, nc);
}

// round 13
// speedup vs baseline: 1.5070x; 1.0101x over previous
#include <cuda_runtime.h>
#include <cuda_bf16.h>
#include <cuda_fp16.h>
#include <cstdint>

#define NN 50000
#define EE 800000
#define TOT (EE + NN)
#define NB 196                                  // scan blocks: ceil(50000/256)

// ---------------- scratch (static device globals; no allocations) ----------------
__device__ __half   g_h16[2][(size_t)NN * 128];  // per-chain GEMM output (fp16, pre-bias)
__device__ float    g_z1[2][(size_t)NN * 128];   // xZ1 (real), xfZ1 (fake)
__device__ uint32_t g_wh[2][64 * 128];           // fp16 hi of 32*W, k-pair-packed half2, per layer
__device__ uint32_t g_wl[2][64 * 128];           // fp16 lo of 32*W
__device__ float    g_as[2][NN * 2];             // alpha_src per node per head
__device__ float    g_ad[2][NN * 2];             // alpha_dst per node per head
__device__ int      g_counts[2][NN];
__device__ int      g_part[2][256];              // scan partials / offsets
__device__ int      g_rowstart[2][NN + 1];
__device__ int      g_cursor[2][NN];
__device__ int      g_csr[2][TOT];               // incoming-edge source lists (CSR by dst)

#define W_SCALE     32.0f
#define W_SCALE_INV 0.03125f

__device__ __forceinline__ float lrelu(float v, float s) { return v > 0.f ? v : s * v; }

// fp16 m16n8k16 MMA, fp32 accumulate
__device__ __forceinline__ void mma_f16(float* d, const uint32_t* a, const uint32_t* b) {
    asm volatile(
        "mma.sync.aligned.m16n8k16.row.col.f32.f16.f16.f32 "
        "{%0,%1,%2,%3}, {%4,%5,%6,%7}, {%8,%9}, {%0,%1,%2,%3};\n"
        : "+f"(d[0]), "+f"(d[1]), "+f"(d[2]), "+f"(d[3])
        : "r"(a[0]), "r"(a[1]), "r"(a[2]), "r"(a[3]), "r"(b[0]), "r"(b[1]));
}

// split f32 pair -> fp16 hi half2 + lo half2
__device__ __forceinline__ void split_h2(float x, float y, uint32_t& h, uint32_t& l) {
    __half2 hh = __floats2half2_rn(x, y);
    float2 b = __half22float2(hh);
    __half2 ll = __floats2half2_rn(x - b.x, y - b.y);
    h = *(uint32_t*)&hh;
    l = *(uint32_t*)&ll;
}

// ---------------- W pre-split: 32*W -> fp16 hi/lo, packed half2 along k ----------------
__global__ void split_w_kernel(const float* __restrict__ W, int layer) {
    int i = blockIdx.x * blockDim.x + threadIdx.x;   // 8192 = 64kk * 128n
    int kk = i >> 7, n = i & 127;
    float w0 = W[(2 * kk) * 128 + n] * W_SCALE;
    float w1 = W[(2 * kk + 1) * 128 + n] * W_SCALE;
    uint32_t h, l;
    split_h2(w0, w1, h, l);
    g_wh[layer][i] = h;
    g_wl[layer][i] = l;
}

// ---------------- CSR build ----------------
__global__ void hist_kernel(const int* __restrict__ ei, int g) {
    int i = blockIdx.x * blockDim.x + threadIdx.x;
    if (i < EE) atomicAdd(&g_counts[g][ei[EE + i]], 1);
}

__global__ void partial_kernel(int g) {
    __shared__ int sh[256];
    const int t = threadIdx.x;
    int i = blockIdx.x * 256 + t;
    int v = (i < NN) ? g_counts[g][i] + 1 : 0;
    sh[t] = v;
    __syncthreads();
#pragma unroll
    for (int off = 128; off >= 1; off >>= 1) {
        if (t < off) sh[t] += sh[t + off];
        __syncthreads();
    }
    if (t == 0) g_part[g][blockIdx.x] = sh[0];
}

__global__ void scan_partials_kernel(int g) {
    __shared__ int sh[256];
    const int t = threadIdx.x;
    int v = (t < NB) ? g_part[g][t] : 0;
    sh[t] = v;
    __syncthreads();
#pragma unroll
    for (int off = 1; off < 256; off <<= 1) {
        int u = (t >= off) ? sh[t - off] : 0;
        __syncthreads();
        sh[t] += u;
        __syncthreads();
    }
    if (t < NB) g_part[g][t] = sh[t] - v;        // exclusive offset
    if (t == NB - 1) g_rowstart[g][NN] = sh[t];  // total
}

__global__ void rowstart_kernel(int g) {
    __shared__ int sh[256];
    const int t = threadIdx.x;
    int i = blockIdx.x * 256 + t;
    int v = (i < NN) ? g_counts[g][i] + 1 : 0;
    sh[t] = v;
    __syncthreads();
#pragma unroll
    for (int off = 1; off < 256; off <<= 1) {
        int u = (t >= off) ? sh[t - off] : 0;
        __syncthreads();
        sh[t] += u;
        __syncthreads();
    }
    if (i < NN) {
        int r = g_part[g][blockIdx.x] + sh[t] - v;
        g_rowstart[g][i] = r;
        g_cursor[g][i] = r;
    }
}

__global__ void scatter_kernel(const int* __restrict__ ei, int g) {
    int i = blockIdx.x * blockDim.x + threadIdx.x;
    if (i >= TOT) return;
    int src, dst;
    if (i < EE) { src = ei[i]; dst = ei[EE + i]; }
    else        { src = i - EE; dst = src; }
    int p = atomicAdd(&g_cursor[g][dst], 1);
    g_csr[g][p] = src;
}

// ---------------- GEMM (fp16 2-split) + fused alpha epilogue ----------------
#define XS2 9                                    // X smem stride (half2 units per row)
#define WS2 132                                  // W smem stride (half2 units per kk row)
__global__ __launch_bounds__(256) void gemm_kernel(const float* __restrict__ X,
                                                   const uint32_t* __restrict__ WH,
                                                   const uint32_t* __restrict__ WL,
                                                   const float* __restrict__ a_src,
                                                   const float* __restrict__ a_dst,
                                                   int gidx,
                                                   __half* __restrict__ O16) {
    __shared__ uint32_t XsH[128 * XS2];
    __shared__ uint32_t XsL[128 * XS2];
    __shared__ uint32_t WsH[8 * WS2];
    __shared__ uint32_t WsL[8 * WS2];
    __shared__ float As[128];
    __shared__ float Ad[128];

    const int t    = threadIdx.x;
    const int lane = t & 31;
    const int wid  = t >> 5;
    const int warpM = wid >> 1;                  // 0..3
    const int warpN = wid & 1;                   // 0..1  (== head)
    const int m0 = warpM * 32;
    const int n0 = warpN * 64;
    const int g  = lane >> 2;                    // 0..7
    const int tg = lane & 3;                     // 0..3
    const int row0 = blockIdx.x * 128;

    if (t < 128) { As[t] = a_src[t] * W_SCALE_INV; Ad[t] = a_dst[t] * W_SCALE_INV; }

    float acc[2][8][4];
#pragma unroll
    for (int mt = 0; mt < 2; mt++)
#pragma unroll
        for (int nt = 0; nt < 8; nt++)
#pragma unroll
            for (int j = 0; j < 4; j++) acc[mt][nt][j] = 0.f;

    const int rX  = t >> 1;                      // X rows: 0..127 (2 threads/row)
    const int kqX = (t & 1) * 2;                 // float4 index base: 0 or 2
    const int kkW = t >> 5;                      // W kk row: 0..7
    const int n4W = t & 31;                      // W uint4 col: 0..31

    for (int kc = 0; kc < 8; kc++) {             // 8 chunks of K=16
        __syncthreads();
#pragma unroll
        for (int q = 0; q < 2; q++) {
            int kq = kqX + q;                    // 0..3 (float4 within chunk)
            int row = row0 + rX; if (row >= NN) row = NN - 1;
            float4 v = *(const float4*)(X + (size_t)row * 128 + kc * 16 + kq * 4);
            uint32_t h0, l0, h1, l1;
            split_h2(v.x, v.y, h0, l0);
            split_h2(v.z, v.w, h1, l1);
            XsH[rX * XS2 + kq * 2]     = h0;
            XsH[rX * XS2 + kq * 2 + 1] = h1;
            XsL[rX * XS2 + kq * 2]     = l0;
            XsL[rX * XS2 + kq * 2 + 1] = l1;
        }
        *(uint4*)&WsH[kkW * WS2 + n4W * 4] =
            *(const uint4*)(WH + (kc * 8 + kkW) * 128 + n4W * 4);
        *(uint4*)&WsL[kkW * WS2 + n4W * 4] =
            *(const uint4*)(WL + (kc * 8 + kkW) * 128 + n4W * 4);
        __syncthreads();

        uint32_t ah[2][4], al[2][4];
#pragma unroll
        for (int mt = 0; mt < 2; mt++) {
            int mr = m0 + mt * 16;
            ah[mt][0] = XsH[(mr + g)     * XS2 + tg];
            ah[mt][1] = XsH[(mr + g + 8) * XS2 + tg];
            ah[mt][2] = XsH[(mr + g)     * XS2 + tg + 4];
            ah[mt][3] = XsH[(mr + g + 8) * XS2 + tg + 4];
            al[mt][0] = XsL[(mr + g)     * XS2 + tg];
            al[mt][1] = XsL[(mr + g + 8) * XS2 + tg];
            al[mt][2] = XsL[(mr + g)     * XS2 + tg + 4];
            al[mt][3] = XsL[(mr + g + 8) * XS2 + tg + 4];
        }
#pragma unroll
        for (int nt = 0; nt < 8; nt++) {
            const int nc = n0 + nt * 8 + g;
            uint32_t bh[2], bl[2];
            bh[0] = WsH[tg * WS2 + nc];
            bh[1] = WsH[(tg + 4) * WS2 + nc];
            bl[0] = WsL[tg * WS2 + nc];
            bl[1] = WsL[(tg + 4) * WS2 + nc];
#pragma unroll
            for (int mt = 0; mt < 2; mt++) {
                mma_f16(acc[mt][nt], ah[mt], bh);
                mma_f16(acc[mt][nt], al[mt], bh);
                mma_f16(acc[mt][nt], ah[mt], bl);
            }
        }
    }

    // ---- epilogue: fp16 H store (acc/32) + fused alpha dots (As/Ad pre-scaled) ----
#pragma unroll
    for (int mt = 0; mt < 2; mt++) {
        int rowA = row0 + m0 + mt * 16 + g;
        int rowB = rowA + 8;
        float sA = 0.f, dA = 0.f, sB = 0.f, dB = 0.f;
#pragma unroll
        for (int nt = 0; nt < 8; nt++) {
            int col = n0 + nt * 8 + tg * 2;
            float a0s = As[col], a1s = As[col + 1];
            float a0d = Ad[col], a1d = Ad[col + 1];
            sA += acc[mt][nt][0] * a0s + acc[mt][nt][1] * a1s;
            dA += acc[mt][nt][0] * a0d + acc[mt][nt][1] * a1d;
            sB += acc[mt][nt][2] * a0s + acc[mt][nt][3] * a1s;
            dB += acc[mt][nt][2] * a0d + acc[mt][nt][3] * a1d;
            __half2 hA = __floats2half2_rn(acc[mt][nt][0] * W_SCALE_INV,
                                           acc[mt][nt][1] * W_SCALE_INV);
            __half2 hB = __floats2half2_rn(acc[mt][nt][2] * W_SCALE_INV,
                                           acc[mt][nt][3] * W_SCALE_INV);
            if (rowA < NN) *(__half2*)(O16 + (size_t)rowA * 128 + col) = hA;
            if (rowB < NN) *(__half2*)(O16 + (size_t)rowB * 128 + col) = hB;
        }
#pragma unroll
        for (int off = 1; off <= 2; off <<= 1) {
            sA += __shfl_xor_sync(0xffffffffu, sA, off);
            dA += __shfl_xor_sync(0xffffffffu, dA, off);
            sB += __shfl_xor_sync(0xffffffffu, sB, off);
            dB += __shfl_xor_sync(0xffffffffu, dB, off);
        }
        if (tg == 0) {
            if (rowA < NN) {
                g_as[gidx][rowA * 2 + warpN] = sA;
                g_ad[gidx][rowA * 2 + warpN] = dA;
            }
            if (rowB < NN) {
                g_as[gidx][rowB * 2 + warpN] = sB;
                g_ad[gidx][rowB * 2 + warpN] = dB;
            }
        }
    }
}

// ---------------- softmax aggregation: one warp per destination node ----------------
__global__ void agg_kernel(const __half* __restrict__ H16, int g,
                           const float* __restrict__ bias,
                           float* __restrict__ out, int do_relu) {
    int w = (blockIdx.x * blockDim.x + threadIdx.x) >> 5;
    if (w >= NN) return;
    int lane = threadIdx.x & 31;
    int beg = g_rowstart[g][w], end = g_rowstart[g][w + 1];
    float ad0 = g_ad[g][w * 2], ad1 = g_ad[g][w * 2 + 1];

    float m0 = -1e30f, m1 = -1e30f, s0 = 0.f, s1 = 0.f;
    for (int e = beg + lane; e < end; e += 32) {
        int src = g_csr[g][e];
        float2 av = *(const float2*)&g_as[g][src * 2];
        float e0 = lrelu(av.x + ad0, 0.2f);
        float e1 = lrelu(av.y + ad1, 0.2f);
        if (e0 > m0) { s0 = s0 * __expf(m0 - e0) + 1.f; m0 = e0; } else s0 += __expf(e0 - m0);
        if (e1 > m1) { s1 = s1 * __expf(m1 - e1) + 1.f; m1 = e1; } else s1 += __expf(e1 - m1);
    }
#pragma unroll
    for (int off = 16; off >= 1; off >>= 1) {
        float mo = __shfl_xor_sync(0xffffffffu, m0, off);
        float so = __shfl_xor_sync(0xffffffffu, s0, off);
        float mn = fmaxf(m0, mo);
        s0 = s0 * __expf(m0 - mn) + so * __expf(mo - mn); m0 = mn;
        mo = __shfl_xor_sync(0xffffffffu, m1, off);
        so = __shfl_xor_sync(0xffffffffu, s1, off);
        mn = fmaxf(m1, mo);
        s1 = s1 * __expf(m1 - mn) + so * __expf(mo - mn); m1 = mn;
    }
    float inv0 = 1.f / s0;
    float inv1 = 1.f / s1;

    const int col  = lane * 4;
    const int head = lane >> 4;
    float4 acc = make_float4(0.f, 0.f, 0.f, 0.f);

    for (int base = beg; base < end; base += 32) {
        int cnt = end - base; if (cnt > 32) cnt = 32;
        int   sidx = 0; float aa0 = 0.f, aa1 = 0.f;
        if (lane < cnt) {
            sidx = g_csr[g][base + lane];
            float2 av = *(const float2*)&g_as[g][sidx * 2];
            float e0 = lrelu(av.x + ad0, 0.2f);
            float e1 = lrelu(av.y + ad1, 0.2f);
            aa0 = __expf(e0 - m0) * inv0;
            aa1 = __expf(e1 - m1) * inv1;
        }
#pragma unroll 4
        for (int j = 0; j < cnt; j++) {
            int   sj  = __shfl_sync(0xffffffffu, sidx, j);
            float a0j = __shfl_sync(0xffffffffu, aa0, j);
            float a1j = __shfl_sync(0xffffffffu, aa1, j);
            float aj  = head ? a1j : a0j;
            uint2 u = *(const uint2*)(H16 + (size_t)sj * 128 + col);
            float2 f0 = __half22float2(*(__half2*)&u.x);
            float2 f1 = __half22float2(*(__half2*)&u.y);
            acc.x += aj * f0.x; acc.y += aj * f0.y;
            acc.z += aj * f1.x; acc.w += aj * f1.y;
        }
    }

    float4 bv = *(const float4*)(bias + col);
    float4 r = make_float4(acc.x + bv.x, acc.y + bv.y, acc.z + bv.z, acc.w + bv.w);
    if (do_relu) {
        r.x = fmaxf(r.x, 0.f); r.y = fmaxf(r.y, 0.f);
        r.z = fmaxf(r.z, 0.f); r.w = fmaxf(r.w, 0.f);
    }
    *(float4*)(out + (size_t)w * 128 + col) = r;
}

// ---------------- tprob = leaky_relu(xZ2 @ Wp + bp, 0.01) ----------------
__global__ void tprob_kernel(const float* __restrict__ Z, const float* __restrict__ Wp,
                             const float* __restrict__ bp, float* __restrict__ out) {
    int w = (blockIdx.x * blockDim.x + threadIdx.x) >> 5;
    if (w >= NN) return;
    int lane = threadIdx.x & 31;
    int col = lane * 4;
    float4 v  = *(const float4*)(Z + (size_t)w * 128 + col);
    float4 p0 = *(const float4*)(Wp + col * 2);
    float4 p1 = *(const float4*)(Wp + col * 2 + 4);
    float a0 = v.x * p0.x + v.y * p0.z + v.z * p1.x + v.w * p1.z;
    float a1 = v.x * p0.y + v.y * p0.w + v.z * p1.y + v.w * p1.w;
#pragma unroll
    for (int off = 16; off >= 1; off >>= 1) {
        a0 += __shfl_xor_sync(0xffffffffu, a0, off);
        a1 += __shfl_xor_sync(0xffffffffu, a1, off);
    }
    if (lane == 0) {
        float o0 = lrelu(a0 + bp[0], 0.01f);
        float o1 = lrelu(a1 + bp[1], 0.01f);
        *(float2*)(out + (size_t)w * 2) = make_float2(o0, o1);
    }
}

// ---------------- fused y heads ----------------
__global__ void heads_kernel(const float* __restrict__ Z0, const float* __restrict__ Z1,
                             const int* __restrict__ treat, const int* __restrict__ control,
                             const float* __restrict__ WyS, const float* __restrict__ byS,
                             const float* __restrict__ Wy1, const float* __restrict__ by1,
                             const float* __restrict__ Wy0, const float* __restrict__ by0,
                             float* __restrict__ out, int nt, int nc) {
    __shared__ float Ws[128 * 64];
    __shared__ float bs[64];
    __shared__ float wy[64];
    __shared__ float byv;

    const int y = blockIdx.y;
    const float* Z   = (y == 0 || y == 2) ? Z0 : Z1;
    const int*   idx = (y < 2) ? treat : control;
    const float* Wy  = (y == 0 || y == 3) ? Wy1 : Wy0;
    const float* by  = (y == 0 || y == 3) ? by1 : by0;
    const int    cnt = (y < 2) ? nt : nc;
    float* yout = out + (y == 0 ? 0 : y == 1 ? nt : y == 2 ? 2 * nt : 2 * nt + nc);

    const int t = threadIdx.x;                   // 256 threads = 8 warps
#pragma unroll
    for (int i = 0; i < 32; i++) Ws[t + i * 256] = WyS[t + i * 256];
    if (t < 64) { bs[t] = byS[t]; wy[t] = Wy[t]; }
    if (t == 0) byv = by[0];
    __syncthreads();

    const int warp = t >> 5, lane = t & 31;
    for (int i = blockIdx.x * 8 + warp; i < cnt; i += gridDim.x * 8) {
        int node = idx[i];
        const float* z = Z + (size_t)node * 128;
        float za = z[lane], zb = z[lane + 32], zc = z[lane + 64], zd = z[lane + 96];
        float s0 = bs[lane], s1 = bs[lane + 32];
#pragma unroll
        for (int k = 0; k < 128; k++) {
            float src = (k < 32) ? za : (k < 64) ? zb : (k < 96) ? zc : zd;
            float zk = __shfl_sync(0xffffffffu, src, k & 31);
            s0 += zk * Ws[k * 64 + lane];
            s1 += zk * Ws[k * 64 + lane + 32];
        }
        s0 = lrelu(s0, 0.01f);
        s1 = lrelu(s1, 0.01f);
        float p = s0 * wy[lane] + s1 * wy[lane + 32];
#pragma unroll
        for (int off = 16; off >= 1; off >>= 1) p += __shfl_xor_sync(0xffffffffu, p, off);
        if (lane == 0) yout[i] = lrelu(p + byv, 0.01f);
    }
}

// ---------------- launch ----------------
static void build_csr(cudaStream_t s, const int* ei, int g, int* counts_ptr) {
    cudaMemsetAsync(counts_ptr, 0, NN * sizeof(int), s);
    hist_kernel<<<(EE + 255) / 256, 256, 0, s>>>(ei, g);
    partial_kernel<<<NB, 256, 0, s>>>(g);
    scan_partials_kernel<<<1, 256, 0, s>>>(g);
    rowstart_kernel<<<NB, 256, 0, s>>>(g);
    scatter_kernel<<<(TOT + 255) / 256, 256, 0, s>>>(ei, g);
}

extern "C" void kernel_launch(void* const* d_in, const int* in_sizes, int n_in,
                              void* d_out, int out_size) {
    const float* x       = (const float*)d_in[0];
    const int*   ei      = (const int*)d_in[1];
    const float* fx      = (const float*)d_in[2];
    const int*   fei     = (const int*)d_in[3];
    const int*   treat   = (const int*)d_in[4];
    const int*   control = (const int*)d_in[5];
    const float* W1      = (const float*)d_in[6];
    const float* as1     = (const float*)d_in[7];
    const float* ad1     = (const float*)d_in[8];
    const float* b1      = (const float*)d_in[9];
    const float* W2      = (const float*)d_in[10];
    const float* as2     = (const float*)d_in[11];
    const float* ad2     = (const float*)d_in[12];
    const float* b2      = (const float*)d_in[13];
    const float* WyS     = (const float*)d_in[14];
    const float* byS     = (const float*)d_in[15];
    const float* Wy1     = (const float*)d_in[16];
    const float* by1     = (const float*)d_in[17];
    const float* Wy0     = (const float*)d_in[18];
    const float* by0     = (const float*)d_in[19];
    const float* Wp      = (const float*)d_in[20];
    const float* bp      = (const float*)d_in[21];
    float* out = (float*)d_out;
    const int nt = in_sizes[4];
    const int nc = in_sizes[5];

    __half*   h16    = nullptr;
    float*    z1     = nullptr;
    int*      counts = nullptr;
    uint32_t* wh     = nullptr;
    uint32_t* wl     = nullptr;
    cudaGetSymbolAddress((void**)&h16, g_h16);
    cudaGetSymbolAddress((void**)&z1, g_z1);
    cudaGetSymbolAddress((void**)&counts, g_counts);
    cudaGetSymbolAddress((void**)&wh, g_wh);
    cudaGetSymbolAddress((void**)&wl, g_wl);
    __half* hA = h16;
    __half* hB = h16 + (size_t)NN * 128;
    float* z1a = z1;
    float* z1b = z1 + (size_t)NN * 128;
    int* cntA = counts;
    int* cntB = counts + NN;
    uint32_t* wh1 = wh;
    uint32_t* wh2 = wh + 64 * 128;
    uint32_t* wl1 = wl;
    uint32_t* wl2 = wl + 64 * 128;

    const size_t OFF_XZ2  = (size_t)2 * nt + (size_t)2 * nc;
    const size_t OFF_XFZ2 = OFF_XZ2 + (size_t)NN * 128;
    const size_t OFF_TP   = OFF_XFZ2 + (size_t)NN * 128;

    static cudaStream_t sB = nullptr, sC = nullptr, sD = nullptr;
    static cudaEvent_t evFork = nullptr, evJoin = nullptr, evCsrA = nullptr, evCsrB = nullptr;
    static cudaEvent_t evGA1 = nullptr;
    if (sB == nullptr) {
        cudaStreamCreateWithFlags(&sB, cudaStreamNonBlocking);
        cudaStreamCreateWithFlags(&sC, cudaStreamNonBlocking);
        cudaStreamCreateWithFlags(&sD, cudaStreamNonBlocking);
        cudaEventCreateWithFlags(&evFork, cudaEventDisableTiming);
        cudaEventCreateWithFlags(&evJoin, cudaEventDisableTiming);
        cudaEventCreateWithFlags(&evCsrA, cudaEventDisableTiming);
        cudaEventCreateWithFlags(&evCsrB, cudaEventDisableTiming);
        cudaEventCreateWithFlags(&evGA1, cudaEventDisableTiming);
    }
    cudaStream_t sA = 0;  // legacy default (the captured stream)

    // W splits visible to all streams, then fork
    split_w_kernel<<<32, 256, 0, sA>>>(W1, 0);
    split_w_kernel<<<32, 256, 0, sA>>>(W2, 1);
    cudaEventRecord(evFork, sA);
    cudaStreamWaitEvent(sB, evFork, 0);
    cudaStreamWaitEvent(sC, evFork, 0);
    cudaStreamWaitEvent(sD, evFork, 0);

    const int WARP_BLK = (NN * 32) / 256;        // 6250
    const int GEMM_BLK = (NN + 127) / 128;       // 391

    // ---- CSR builds on side streams (overlap the tensor-heavy slots) ----
    build_csr(sC, ei, 0, cntA);
    cudaEventRecord(evCsrA, sC);
    build_csr(sD, fei, 1, cntB);
    cudaEventRecord(evCsrB, sD);

    // ---- real chain on sA ----
    gemm_kernel<<<GEMM_BLK, 256, 0, sA>>>(x,   wh1, wl1, as1, ad1, 0, hA);
    cudaEventRecord(evGA1, sA);                  // stagger point for chain B
    cudaStreamWaitEvent(sA, evCsrA, 0);          // agg needs the CSR
    agg_kernel<<<WARP_BLK, 256, 0, sA>>>(hA, 0, b1, z1a, 1);
    gemm_kernel<<<GEMM_BLK, 256, 0, sA>>>(z1a, wh2, wl2, as2, ad2, 0, hA);
    agg_kernel<<<WARP_BLK, 256, 0, sA>>>(hA, 0, b2, out + OFF_XZ2, 0);
    tprob_kernel<<<WARP_BLK, 256, 0, sA>>>(out + OFF_XZ2, Wp, bp, out + OFF_TP);

    // ---- fake chain on sB, staggered one stage behind chain A ----
    cudaStreamWaitEvent(sB, evGA1, 0);           // gemmB1 co-runs with aggA1
    gemm_kernel<<<GEMM_BLK, 256, 0, sB>>>(fx,  wh1, wl1, as1, ad1, 1, hB);
    cudaStreamWaitEvent(sB, evCsrB, 0);
    agg_kernel<<<WARP_BLK, 256, 0, sB>>>(hB, 1, b1, z1b, 1);
    gemm_kernel<<<GEMM_BLK, 256, 0, sB>>>(z1b, wh2, wl2, as2, ad2, 1, hB);
    agg_kernel<<<WARP_BLK, 256, 0, sB>>>(hB, 1, b2, out + OFF_XFZ2, 0);

    // join
    cudaEventRecord(evJoin, sB);
    cudaStreamWaitEvent(sA, evJoin, 0);

    heads_kernel<<<dim3(32, 4), 256, 0, sA>>>(out + OFF_XZ2, out + OFF_XFZ2, treat, control,
                                              WyS, byS, Wy1, by1, Wy0, by0, out, nt, nc);
}